// round 12
// baseline (speedup 1.0000x reference)
#include <cuda_runtime.h>
#include <cuda_fp16.h>
#include <cuda_bf16.h>
#include <cstdint>
#include <math.h>

// ---------------- problem constants ----------------
#define NS    6400          // SAMPLE*SAMPLE patches per image
#define CCH   49            // PATCH*PATCH channels
#define IMGW  512
#define GW    169           // (512-7)/3 + 1 patch-grid size
#define EPSF  2.2204460492503131e-16f
#define LAMB  0.05f
#define KST   168           // row stride in bf16 (160 active K + 8 pad)
#define DPAD  72            // d staging row stride in halves (64 + 8 pad)

// ---------------- device scratch ----------------
__device__ int   g_base_t[NS];
__device__ int   g_base_r[NS];
__device__ float g_ymean[CCH];
__device__ __nv_bfloat16 g_xr[(size_t)NS * KST];  // target rows [hi49|hi49|lo49|0...]
__device__ __nv_bfloat16 g_yr[(size_t)NS * KST];  // refer  rows [hi49|lo49|hi49|0...]
__device__ __half g_dh[(size_t)NS * NS];          // 81.92 MB distance matrix (fp16)
__device__ unsigned long long g_amin[NS];
__device__ int   g_cnt[NS];
__device__ float g_rowloss[NS];

// ---------------- warp-mma helpers ----------------
__device__ __forceinline__ uint32_t smem_to_u32(const void* p) {
    uint32_t a;
    asm("{ .reg .u64 t; cvta.to.shared.u64 t, %1; cvt.u32.u64 %0, t; }" : "=r"(a) : "l"(p));
    return a;
}
__device__ __forceinline__ void ldsm_x4(uint32_t& r0, uint32_t& r1, uint32_t& r2, uint32_t& r3,
                                        uint32_t addr) {
    asm volatile("ldmatrix.sync.aligned.m8n8.x4.shared.b16 {%0,%1,%2,%3}, [%4];"
                 : "=r"(r0), "=r"(r1), "=r"(r2), "=r"(r3) : "r"(addr));
}
__device__ __forceinline__ void mma16816(float* c, const uint32_t* a, const uint32_t* b) {
    asm volatile("mma.sync.aligned.m16n8k16.row.col.f32.bf16.bf16.f32 "
                 "{%0,%1,%2,%3}, {%4,%5,%6,%7}, {%8,%9}, {%0,%1,%2,%3};"
                 : "+f"(c[0]), "+f"(c[1]), "+f"(c[2]), "+f"(c[3])
                 : "r"(a[0]), "r"(a[1]), "r"(a[2]), "r"(a[3]), "r"(b[0]), "r"(b[1]));
}

// ---------------- 1) grid-sample nearest indices (+ init amin/cnt) ----------------
__global__ void k_idx(const float* __restrict__ tfield, const float* __restrict__ rfield) {
    int i = blockIdx.x * blockDim.x + threadIdx.x;
    if (i < NS) { g_amin[i] = ~0ull; g_cnt[i] = 0; }
    if (i >= 2 * NS) return;
    const float* f = (i < NS) ? tfield : rfield;
    int p = (i < NS) ? i : (i - NS);
    float gx = __fadd_rn(__fmul_rn(f[2 * p + 0], 2.0f), -1.0f);
    float gy = __fadd_rn(__fmul_rn(f[2 * p + 1], 2.0f), -1.0f);
    float fx = __fmul_rn(__fadd_rn(__fmul_rn(__fadd_rn(gx, 1.0f), (float)GW), -1.0f), 0.5f);
    float fy = __fmul_rn(__fadd_rn(__fmul_rn(__fadd_rn(gy, 1.0f), (float)GW), -1.0f), 0.5f);
    int ix = (int)rintf(fx); ix = ix < 0 ? 0 : (ix > GW - 1 ? GW - 1 : ix);
    int iy = (int)rintf(fy); iy = iy < 0 ? 0 : (iy > GW - 1 ? GW - 1 : iy);
    int base = (iy * 3) * IMGW + ix * 3;
    if (i < NS) g_base_t[p] = base; else g_base_r[p] = base;
}

// ---------------- 2) refer patch channel mean ----------------
__global__ void k_mean(const float* __restrict__ rimg) {
    int c = blockIdx.x;
    int off = (c / 7) * IMGW + (c % 7);
    int t = threadIdx.x;
    float s = 0.0f;
    for (int p = t; p < NS; p += 256) s += rimg[g_base_r[p] + off];
    __shared__ float sm[256];
    sm[t] = s; __syncthreads();
    for (int st = 128; st; st >>= 1) { if (t < st) sm[t] += sm[t + st]; __syncthreads(); }
    if (t == 0) g_ymean[c] = sm[0] * (1.0f / (float)NS);
}

// ---------------- 3) features -> bf16 hi/lo split rows (smem-staged coalesced writes) ----------------
// X row: [hi(49) | hi(49) | lo(49) | 0] ; Y row: [hi(49) | lo(49) | hi(49) | 0]
// X.Y = hi.hi + hi.lo + lo.hi  (drops only lo.lo ~2^-18)
__global__ void __launch_bounds__(128) k_feat(const float* __restrict__ timg,
                                              const float* __restrict__ rimg) {
    __shared__ __nv_bfloat16 srow[128 * KST];   // 43008 B
    int t = threadIdx.x;
    int p = blockIdx.x * 128 + t;               // gridDim.x = 50
    bool is_t = (blockIdx.y == 0);
    const float* img = is_t ? timg : rimg;
    int base = is_t ? g_base_t[p] : g_base_r[p];

    float v[CCH];
    float sq = 0.0f;
#pragma unroll
    for (int c = 0; c < CCH; c++) {
        v[c] = img[base + (c / 7) * IMGW + (c % 7)] - g_ymean[c];
        sq += v[c] * v[c];
    }
    float inv = 1.0f / (sqrtf(sq) + EPSF);
    __nv_bfloat16* row = &srow[t * KST];
#pragma unroll
    for (int c = 0; c < CCH; c++) {
        float val = v[c] * inv;
        __nv_bfloat16 hi = __float2bfloat16(val);
        __nv_bfloat16 lo = __float2bfloat16(val - __bfloat162float(hi));
        if (is_t) { row[c] = hi; row[49 + c] = hi; row[98 + c] = lo; }
        else      { row[c] = hi; row[49 + c] = lo; row[98 + c] = hi; }
    }
    for (int k = 147; k < KST; k++) row[k] = __float2bfloat16(0.0f);
    __syncthreads();

    // coalesced block copy: 128 rows x 21 uint4 contiguous
    uint4* dst = (uint4*)((is_t ? g_xr : g_yr) + (size_t)(blockIdx.x * 128) * KST);
    const uint4* src = (const uint4*)srow;
    for (int i = t; i < 128 * 21; i += 128) dst[i] = src[i];
}

// ---------------- 4) tensor GEMM: mma.sync m16n8k16 bf16, 128x64 tile, 3 CTAs/SM ----------------
// 8 warps: warp (wid&3) -> 32-row band, (wid>>2) -> 32-col band. K = 160 (10 chunks).
#define GEMM_SMEM ((128 + 64) * KST * 2)   // 64512 B
__global__ void __launch_bounds__(256, 3) k_gemm() {
    extern __shared__ __nv_bfloat16 smbf[];
    __nv_bfloat16* Xs = smbf;                  // [128][KST]
    __nv_bfloat16* Ys = smbf + 128 * KST;      // [64][KST]
    __half* Ds = (__half*)smbf;                // reused after mainloop: [128][DPAD]
    int t = threadIdx.x, wid = t >> 5, lid = t & 31;
    int bx = blockIdx.x, by = blockIdx.y;      // 100 x 50

    {   // tile loads: X 128 rows, Y 64 rows x 21 uint4 each, contiguous
        const uint4* xs = (const uint4*)&g_xr[(size_t)(by * 128) * KST];
        const uint4* ys = (const uint4*)&g_yr[(size_t)(bx * 64) * KST];
        uint4* X4 = (uint4*)Xs; uint4* Y4 = (uint4*)Ys;
        for (int i = t; i < 128 * 21; i += 256) X4[i] = xs[i];
        for (int i = t; i < 64 * 21; i += 256) Y4[i] = ys[i];
    }
    __syncthreads();

    int MR = (wid & 3) * 32, NC = (wid >> 2) * 32;
    uint32_t xbase = smem_to_u32(Xs), ybase = smem_to_u32(Ys);
    int arow = (lid & 7) + ((lid >> 3) & 1) * 8;
    int akof = (lid >> 4) * 8;
    int brow = (lid & 7) + ((lid >> 4) & 1) * 8;
    int bkof = ((lid >> 3) & 1) * 8;

    float acc[2][4][4];
#pragma unroll
    for (int i = 0; i < 2; i++)
#pragma unroll
        for (int j = 0; j < 4; j++)
#pragma unroll
            for (int e = 0; e < 4; e++) acc[i][j][e] = 0.0f;

#pragma unroll
    for (int k = 0; k < 10; k++) {
        int kb = k * 16;
        uint32_t a[2][4];
#pragma unroll
        for (int mt = 0; mt < 2; mt++)
            ldsm_x4(a[mt][0], a[mt][1], a[mt][2], a[mt][3],
                    xbase + ((MR + mt * 16 + arow) * KST + kb + akof) * 2);
        uint32_t b[4][2];
#pragma unroll
        for (int nt2 = 0; nt2 < 2; nt2++)
            ldsm_x4(b[2 * nt2][0], b[2 * nt2][1], b[2 * nt2 + 1][0], b[2 * nt2 + 1][1],
                    ybase + ((NC + nt2 * 16 + brow) * KST + kb + bkof) * 2);
#pragma unroll
        for (int mt = 0; mt < 2; mt++)
#pragma unroll
            for (int nt = 0; nt < 4; nt++)
                mma16816(acc[mt][nt], a[mt], b[nt]);
    }
    __syncthreads();   // done reading Xs/Ys; Ds overwrites X region

    // epilogue: d = max(0.5 - 0.5*sim, 0); float-scan argmin + packed cvt + smem staging
    int g = lid >> 2, tq = lid & 3;
#pragma unroll
    for (int mt = 0; mt < 2; mt++) {
        int rl0 = MR + mt * 16 + g;
        int rl1 = rl0 + 8;
        float v0 = 1e30f, v1 = 1e30f;
        int i0 = 0, i1 = 0;
#pragma unroll
        for (int nt = 0; nt < 4; nt++) {
            int cl = NC + nt * 8 + tq * 2;
            int col = bx * 64 + cl;
            float d00 = fmaxf(fmaf(acc[mt][nt][0], -0.5f, 0.5f), 0.0f);
            float d01 = fmaxf(fmaf(acc[mt][nt][1], -0.5f, 0.5f), 0.0f);
            float d10 = fmaxf(fmaf(acc[mt][nt][2], -0.5f, 0.5f), 0.0f);
            float d11 = fmaxf(fmaf(acc[mt][nt][3], -0.5f, 0.5f), 0.0f);
            uint32_t p0, p1;
            asm("cvt.rn.f16x2.f32 %0, %1, %2;" : "=r"(p0) : "f"(d01), "f"(d00));
            asm("cvt.rn.f16x2.f32 %0, %1, %2;" : "=r"(p1) : "f"(d11), "f"(d10));
            *(uint32_t*)&Ds[rl0 * DPAD + cl] = p0;
            *(uint32_t*)&Ds[rl1 * DPAD + cl] = p1;
            if (d00 < v0) { v0 = d00; i0 = col; }
            if (d01 < v0) { v0 = d01; i0 = col + 1; }
            if (d10 < v1) { v1 = d10; i1 = col; }
            if (d11 < v1) { v1 = d11; i1 = col + 1; }
        }
#pragma unroll
        for (int o = 1; o < 4; o <<= 1) {
            float vo0 = __shfl_xor_sync(0xffffffffu, v0, o);
            int   io0 = __shfl_xor_sync(0xffffffffu, i0, o);
            if (vo0 < v0 || (vo0 == v0 && io0 < i0)) { v0 = vo0; i0 = io0; }
            float vo1 = __shfl_xor_sync(0xffffffffu, v1, o);
            int   io1 = __shfl_xor_sync(0xffffffffu, i1, o);
            if (vo1 < v1 || (vo1 == v1 && io1 < i1)) { v1 = vo1; i1 = io1; }
        }
        if (tq == 0) {
            atomicMin(&g_amin[by * 128 + rl0],
                      ((unsigned long long)__float_as_uint(v0) << 32) | (unsigned)i0);
            atomicMin(&g_amin[by * 128 + rl1],
                      ((unsigned long long)__float_as_uint(v1) << 32) | (unsigned)i1);
        }
    }
    __syncthreads();

    // coalesced store: 128 rows x 8 uint4 (128 B per row)
    for (int i = t; i < 128 * 8; i += 256) {
        int row = i >> 3, c8 = i & 7;
        *(uint4*)&g_dh[(size_t)(by * 128 + row) * NS + bx * 64 + c8 * 8] =
            *(const uint4*)&Ds[row * DPAD + c8 * 8];
    }
}

// ---------------- 5) occurrence counts ----------------
__global__ void k_cnt() {
    int p = blockIdx.x * 256 + threadIdx.x;
    if (p < NS) {
        unsigned q = (unsigned)(g_amin[p] & 0xffffffffu);
        atomicAdd(&g_cnt[q], 1);
    }
}

// ---------------- 6) per-row min + sum-exp -> row loss (8 rows per block) ----------------
__global__ void __launch_bounds__(256) k_row() {
    extern __shared__ float dyn[];
    float* occ = dyn;               // [NS]
    float* sd  = dyn + NS;          // [NS]
    float* sr  = dyn + 2 * NS;      // [8]
    int t = threadIdx.x;

    for (int j = t; j < NS; j += 256) occ[j] = LAMB * (float)g_cnt[j];
    __syncthreads();

#pragma unroll 1
    for (int r = 0; r < 8; r++) {
        int p = blockIdx.x * 8 + r;
        const uint4* drow = (const uint4*)&g_dh[(size_t)p * NS];

        float m = 3.4e38f;
        for (int j8 = t; j8 < NS / 8; j8 += 256) {
            uint4 u = drow[j8];
            const __half* h = (const __half*)&u;
            int j = j8 * 8;
            float lm = 3.4e38f;
#pragma unroll
            for (int e = 0; e < 8; e++) {
                float v = __half2float(h[e]) + occ[j + e];
                sd[j + e] = v;
                lm = fminf(lm, v);
            }
            m = fminf(m, lm);
        }
#pragma unroll
        for (int o = 16; o; o >>= 1) m = fminf(m, __shfl_xor_sync(0xffffffffu, m, o));
        if ((t & 31) == 0) sr[t >> 5] = m;
        __syncthreads();
        if (t == 0) {
            float x = sr[0];
#pragma unroll
            for (int w = 1; w < 8; w++) x = fminf(x, sr[w]);
            sr[0] = x;
        }
        __syncthreads();
        m = sr[0];
        __syncthreads();

        float meps = __fadd_rn(m, EPSF);
        float inv = 1.0f / meps;

        float s = 0.0f;
        for (int j = t; j < NS; j += 256) {
            float rr = sd[j] * inv;
            s += __expf(__fmul_rn(__fadd_rn(1.0f, -rr), 2.0f));
        }
#pragma unroll
        for (int o = 16; o; o >>= 1) s += __shfl_xor_sync(0xffffffffu, s, o);
        if ((t & 31) == 0) sr[t >> 5] = s;
        __syncthreads();
        if (t == 0) {
            float st = 0.0f;
#pragma unroll
            for (int w = 0; w < 8; w++) st += sr[w];
            float emax = __fmul_rn(__fadd_rn(1.0f, -__fmul_rn(m, inv)), 2.0f);
            g_rowloss[p] = logf(st) - emax;
        }
        __syncthreads();
    }
}

// ---------------- 7) final mean ----------------
__global__ void k_final(float* __restrict__ out) {
    int t = threadIdx.x;
    float s = 0.0f;
    for (int p = t; p < NS; p += 256) s += g_rowloss[p];
    __shared__ float sm[256];
    sm[t] = s; __syncthreads();
    for (int st = 128; st; st >>= 1) { if (t < st) sm[t] += sm[t + st]; __syncthreads(); }
    if (t == 0) out[0] = sm[0] * (1.0f / (float)NS);
}

// ---------------- host launch ----------------
extern "C" void kernel_launch(void* const* d_in, const int* in_sizes, int n_in,
                              void* d_out, int out_size) {
    (void)in_sizes; (void)n_in; (void)out_size;
    const float* timg   = (const float*)d_in[0];
    const float* rimg   = (const float*)d_in[1];
    const float* tfield = (const float*)d_in[2];
    const float* rfield = (const float*)d_in[3];
    float* out = (float*)d_out;

    const int ROW_SMEM = (2 * NS + 8) * (int)sizeof(float);          // 51232 B
    cudaFuncSetAttribute(k_gemm, cudaFuncAttributeMaxDynamicSharedMemorySize, GEMM_SMEM);
    cudaFuncSetAttribute(k_row,  cudaFuncAttributeMaxDynamicSharedMemorySize, ROW_SMEM);

    k_idx  <<<50, 256>>>(tfield, rfield);
    k_mean <<<CCH, 256>>>(rimg);
    k_feat <<<dim3(50, 2), 128>>>(timg, rimg);
    k_gemm <<<dim3(100, 50), 256, GEMM_SMEM>>>();
    k_cnt  <<<25, 256>>>();
    k_row  <<<800, 256, ROW_SMEM>>>();
    k_final<<<1, 256>>>(out);
}

// round 13
// speedup vs baseline: 1.2197x; 1.2197x over previous
#include <cuda_runtime.h>
#include <cuda_fp16.h>
#include <cuda_bf16.h>
#include <cstdint>
#include <math.h>

// ---------------- problem constants ----------------
#define NS    6400          // SAMPLE*SAMPLE patches per image
#define CCH   49            // PATCH*PATCH channels
#define IMGW  512
#define GW    169           // (512-7)/3 + 1 patch-grid size
#define EPSF  2.2204460492503131e-16f
#define LAMB  0.05f
#define KST   168           // row stride in bf16 (160 active K + 8 pad)
#define DPAD  72            // d staging row stride in halves (64 + 8 pad)
#define NTILES 5000         // 50 row bands x 100 col tiles
#define NCTA  296           // 2 CTAs x 148 SMs, one wave

// ---------------- device scratch ----------------
__device__ int   g_base_t[NS];
__device__ int   g_base_r[NS];
__device__ float g_ymean[CCH];
__device__ __nv_bfloat16 g_xr[(size_t)NS * KST];  // target rows [hi49|hi49|lo49|0...]
__device__ __nv_bfloat16 g_yr[(size_t)NS * KST];  // refer  rows [hi49|lo49|hi49|0...]
__device__ __half g_dh[(size_t)NS * NS];          // 81.92 MB distance matrix (fp16)
__device__ unsigned long long g_amin[NS];
__device__ int   g_cnt[NS];
__device__ float g_rowloss[NS];

// ---------------- helpers ----------------
__device__ __forceinline__ uint32_t smem_to_u32(const void* p) {
    uint32_t a;
    asm("{ .reg .u64 t; cvta.to.shared.u64 t, %1; cvt.u32.u64 %0, t; }" : "=r"(a) : "l"(p));
    return a;
}
__device__ __forceinline__ void ldsm_x4(uint32_t& r0, uint32_t& r1, uint32_t& r2, uint32_t& r3,
                                        uint32_t addr) {
    asm volatile("ldmatrix.sync.aligned.m8n8.x4.shared.b16 {%0,%1,%2,%3}, [%4];"
                 : "=r"(r0), "=r"(r1), "=r"(r2), "=r"(r3) : "r"(addr));
}
__device__ __forceinline__ void mma16816(float* c, const uint32_t* a, const uint32_t* b) {
    asm volatile("mma.sync.aligned.m16n8k16.row.col.f32.bf16.bf16.f32 "
                 "{%0,%1,%2,%3}, {%4,%5,%6,%7}, {%8,%9}, {%0,%1,%2,%3};"
                 : "+f"(c[0]), "+f"(c[1]), "+f"(c[2]), "+f"(c[3])
                 : "r"(a[0]), "r"(a[1]), "r"(a[2]), "r"(a[3]), "r"(b[0]), "r"(b[1]));
}
__device__ __forceinline__ void cp16(uint32_t dst, const void* src) {
    asm volatile("cp.async.cg.shared.global [%0], [%1], 16;" :: "r"(dst), "l"(src));
}
#define CP_COMMIT() asm volatile("cp.async.commit_group;" ::: "memory")
#define CP_WAIT(n)  asm volatile("cp.async.wait_group %0;" :: "n"(n) : "memory")

// ---------------- 1) grid-sample nearest indices (+ init amin/cnt) ----------------
__global__ void k_idx(const float* __restrict__ tfield, const float* __restrict__ rfield) {
    int i = blockIdx.x * blockDim.x + threadIdx.x;
    if (i < NS) { g_amin[i] = ~0ull; g_cnt[i] = 0; }
    if (i >= 2 * NS) return;
    const float* f = (i < NS) ? tfield : rfield;
    int p = (i < NS) ? i : (i - NS);
    float gx = __fadd_rn(__fmul_rn(f[2 * p + 0], 2.0f), -1.0f);
    float gy = __fadd_rn(__fmul_rn(f[2 * p + 1], 2.0f), -1.0f);
    float fx = __fmul_rn(__fadd_rn(__fmul_rn(__fadd_rn(gx, 1.0f), (float)GW), -1.0f), 0.5f);
    float fy = __fmul_rn(__fadd_rn(__fmul_rn(__fadd_rn(gy, 1.0f), (float)GW), -1.0f), 0.5f);
    int ix = (int)rintf(fx); ix = ix < 0 ? 0 : (ix > GW - 1 ? GW - 1 : ix);
    int iy = (int)rintf(fy); iy = iy < 0 ? 0 : (iy > GW - 1 ? GW - 1 : iy);
    int base = (iy * 3) * IMGW + ix * 3;
    if (i < NS) g_base_t[p] = base; else g_base_r[p] = base;
}

// ---------------- 2) refer patch channel mean ----------------
__global__ void k_mean(const float* __restrict__ rimg) {
    int c = blockIdx.x;
    int off = (c / 7) * IMGW + (c % 7);
    int t = threadIdx.x;
    float s = 0.0f;
    for (int p = t; p < NS; p += 256) s += rimg[g_base_r[p] + off];
    __shared__ float sm[256];
    sm[t] = s; __syncthreads();
    for (int st = 128; st; st >>= 1) { if (t < st) sm[t] += sm[t + st]; __syncthreads(); }
    if (t == 0) g_ymean[c] = sm[0] * (1.0f / (float)NS);
}

// ---------------- 3) features -> bf16 hi/lo split rows (smem-staged coalesced writes) ----------------
// X row: [hi(49) | hi(49) | lo(49) | 0] ; Y row: [hi(49) | lo(49) | hi(49) | 0]
// X.Y = hi.hi + hi.lo + lo.hi  (drops only lo.lo ~2^-18)
__global__ void __launch_bounds__(128) k_feat(const float* __restrict__ timg,
                                              const float* __restrict__ rimg) {
    __shared__ __nv_bfloat16 srow[128 * KST];   // 43008 B
    int t = threadIdx.x;
    int p = blockIdx.x * 128 + t;               // gridDim.x = 50
    bool is_t = (blockIdx.y == 0);
    const float* img = is_t ? timg : rimg;
    int base = is_t ? g_base_t[p] : g_base_r[p];

    float v[CCH];
    float sq = 0.0f;
#pragma unroll
    for (int c = 0; c < CCH; c++) {
        v[c] = img[base + (c / 7) * IMGW + (c % 7)] - g_ymean[c];
        sq += v[c] * v[c];
    }
    float inv = 1.0f / (sqrtf(sq) + EPSF);
    __nv_bfloat16* row = &srow[t * KST];
#pragma unroll
    for (int c = 0; c < CCH; c++) {
        float val = v[c] * inv;
        __nv_bfloat16 hi = __float2bfloat16(val);
        __nv_bfloat16 lo = __float2bfloat16(val - __bfloat162float(hi));
        if (is_t) { row[c] = hi; row[49 + c] = hi; row[98 + c] = lo; }
        else      { row[c] = hi; row[49 + c] = lo; row[98 + c] = hi; }
    }
    for (int k = 147; k < KST; k++) row[k] = __float2bfloat16(0.0f);
    __syncthreads();

    uint4* dst = (uint4*)((is_t ? g_xr : g_yr) + (size_t)(blockIdx.x * 128) * KST);
    const uint4* src = (const uint4*)srow;
    for (int i = t; i < 128 * 21; i += 128) dst[i] = src[i];
}

// ---------------- 4) balanced persistent tensor GEMM ----------------
// 296 CTAs; CTA c owns contiguous tiles [c*5000/296, (c+1)*5000/296) in band-major
// order (band = t/100 -> 128 rows; col = t%100 -> 64 cols). X resident per band
// (<=1 reload/CTA); Y double-buffered via cp.async. 8 warps: 4 m-bands x 2 n-bands.
// smem: X 43008 | Y0 21504 | Y1 21504 | Ds 18432 = 104448 B
#define SM_Y0   (128 * KST * 2)
#define SM_Y1   (192 * KST * 2)
#define SM_DS   (256 * KST * 2)
#define GEMM_SMEM (SM_DS + 128 * DPAD * 2)

__global__ void __launch_bounds__(256, 2) k_gemm() {
    extern __shared__ char smem[];
    uint32_t xs_u = smem_to_u32(smem);
    uint32_t y_u0 = xs_u + SM_Y0, y_u1 = xs_u + SM_Y1;
    __half* Ds = (__half*)(smem + SM_DS);
    int t = threadIdx.x, wid = t >> 5, lid = t & 31;
    int cta = blockIdx.x;
    int ts = (cta * NTILES) / NCTA;
    int te = ((cta + 1) * NTILES) / NCTA;
    int n = te - ts;                      // 16 or 17
    int cur_band = ts / 100;

    // prologue: group1 = X(cur_band) + Y(tile0); group2 = Y(tile1) (or empty)
    {
        const char* xsrc = (const char*)&g_xr[(size_t)(cur_band * 128) * KST];
        for (int i = t; i < 2688; i += 256) cp16(xs_u + i * 16, xsrc + (size_t)i * 16);
        const char* y0 = (const char*)&g_yr[(size_t)((ts % 100) * 64) * KST];
        for (int i = t; i < 1344; i += 256) cp16(y_u0 + i * 16, y0 + (size_t)i * 16);
        CP_COMMIT();
        if (n > 1) {
            const char* y1 = (const char*)&g_yr[(size_t)(((ts + 1) % 100) * 64) * KST];
            for (int i = t; i < 1344; i += 256) cp16(y_u1 + i * 16, y1 + (size_t)i * 16);
        }
        CP_COMMIT();
    }
    CP_WAIT(1);
    __syncthreads();

    int MR = (wid & 3) * 32, NC = (wid >> 2) * 32;
    int arow = (lid & 7) + ((lid >> 3) & 1) * 8;
    int akof = (lid >> 4) * 8;
    int brow = (lid & 7) + ((lid >> 4) & 1) * 8;
    int bkof = ((lid >> 3) & 1) * 8;
    int g = lid >> 2, tq = lid & 3;

    for (int it = 0; it < n; it++) {
        int tile = ts + it;
        int band = tile / 100, col = tile % 100;
        uint32_t yb = (it & 1) ? y_u1 : y_u0;

        if (band != cur_band) {           // <=1 time per CTA
            CP_WAIT(0);
            __syncthreads();
            const char* xsrc = (const char*)&g_xr[(size_t)(band * 128) * KST];
            for (int i = t; i < 2688; i += 256) cp16(xs_u + i * 16, xsrc + (size_t)i * 16);
            CP_COMMIT();
            CP_WAIT(0);
            __syncthreads();
            cur_band = band;
        }

        float acc[2][4][4];
#pragma unroll
        for (int i = 0; i < 2; i++)
#pragma unroll
            for (int j = 0; j < 4; j++)
#pragma unroll
                for (int e = 0; e < 4; e++) acc[i][j][e] = 0.0f;

#pragma unroll
        for (int k = 0; k < 10; k++) {
            int kb = k * 16;
            uint32_t a[2][4];
#pragma unroll
            for (int mt = 0; mt < 2; mt++)
                ldsm_x4(a[mt][0], a[mt][1], a[mt][2], a[mt][3],
                        xs_u + ((MR + mt * 16 + arow) * KST + kb + akof) * 2);
            uint32_t b[4][2];
#pragma unroll
            for (int nt2 = 0; nt2 < 2; nt2++)
                ldsm_x4(b[2 * nt2][0], b[2 * nt2][1], b[2 * nt2 + 1][0], b[2 * nt2 + 1][1],
                        yb + ((NC + nt2 * 16 + brow) * KST + kb + bkof) * 2);
#pragma unroll
            for (int mt = 0; mt < 2; mt++)
#pragma unroll
                for (int nt = 0; nt < 4; nt++)
                    mma16816(acc[mt][nt], a[mt], b[nt]);
        }

        // epilogue: d = max(0.5 - 0.5*sim, 0) -> Ds (smem) + global packed-key argmin
#pragma unroll
        for (int mt = 0; mt < 2; mt++) {
            int rl0 = MR + mt * 16 + g;
            int rl1 = rl0 + 8;
            float v0 = 1e30f, v1 = 1e30f;
            int i0 = 0, i1 = 0;
#pragma unroll
            for (int nt = 0; nt < 4; nt++) {
                int cl = NC + nt * 8 + tq * 2;
                int gcol = col * 64 + cl;
                float d00 = fmaxf(fmaf(acc[mt][nt][0], -0.5f, 0.5f), 0.0f);
                float d01 = fmaxf(fmaf(acc[mt][nt][1], -0.5f, 0.5f), 0.0f);
                float d10 = fmaxf(fmaf(acc[mt][nt][2], -0.5f, 0.5f), 0.0f);
                float d11 = fmaxf(fmaf(acc[mt][nt][3], -0.5f, 0.5f), 0.0f);
                uint32_t p0, p1;
                asm("cvt.rn.f16x2.f32 %0, %1, %2;" : "=r"(p0) : "f"(d01), "f"(d00));
                asm("cvt.rn.f16x2.f32 %0, %1, %2;" : "=r"(p1) : "f"(d11), "f"(d10));
                *(uint32_t*)&Ds[rl0 * DPAD + cl] = p0;
                *(uint32_t*)&Ds[rl1 * DPAD + cl] = p1;
                if (d00 < v0) { v0 = d00; i0 = gcol; }
                if (d01 < v0) { v0 = d01; i0 = gcol + 1; }
                if (d10 < v1) { v1 = d10; i1 = gcol; }
                if (d11 < v1) { v1 = d11; i1 = gcol + 1; }
            }
#pragma unroll
            for (int o = 1; o < 4; o <<= 1) {
                float vo0 = __shfl_xor_sync(0xffffffffu, v0, o);
                int   io0 = __shfl_xor_sync(0xffffffffu, i0, o);
                if (vo0 < v0 || (vo0 == v0 && io0 < i0)) { v0 = vo0; i0 = io0; }
                float vo1 = __shfl_xor_sync(0xffffffffu, v1, o);
                int   io1 = __shfl_xor_sync(0xffffffffu, i1, o);
                if (vo1 < v1 || (vo1 == v1 && io1 < i1)) { v1 = vo1; i1 = io1; }
            }
            if (tq == 0) {
                atomicMin(&g_amin[band * 128 + rl0],
                          ((unsigned long long)__float_as_uint(v0) << 32) | (unsigned)i0);
                atomicMin(&g_amin[band * 128 + rl1],
                          ((unsigned long long)__float_as_uint(v1) << 32) | (unsigned)i1);
            }
        }
        __syncthreads();    // Y[cur] fully read; Ds fully written

        // prefetch tile it+2 into the buffer just consumed
        if (it + 2 < n) {
            int coln = (tile + 2) % 100;
            const char* ysrc = (const char*)&g_yr[(size_t)(coln * 64) * KST];
            for (int i = t; i < 1344; i += 256) cp16(yb + i * 16, ysrc + (size_t)i * 16);
        }
        CP_COMMIT();

        // coalesced store of this tile: 128 rows x 8 uint4 (128 B/row)
        for (int i = t; i < 1024; i += 256) {
            int row = i >> 3, c8 = i & 7;
            *(uint4*)&g_dh[(size_t)(band * 128 + row) * NS + col * 64 + c8 * 8] =
                *(const uint4*)&Ds[row * DPAD + c8 * 8];
        }

        CP_WAIT(1);         // next iteration's Y is complete; <=1 group in flight
        __syncthreads();
    }
}

// ---------------- 5) occurrence counts ----------------
__global__ void k_cnt() {
    int p = blockIdx.x * 256 + threadIdx.x;
    if (p < NS) {
        unsigned q = (unsigned)(g_amin[p] & 0xffffffffu);
        atomicAdd(&g_cnt[q], 1);
    }
}

// ---------------- 6) per-row min + sum-exp -> row loss (8 rows per block) ----------------
__global__ void __launch_bounds__(256) k_row() {
    extern __shared__ float dyn[];
    float* occ = dyn;               // [NS]
    float* sd  = dyn + NS;          // [NS]
    float* sr  = dyn + 2 * NS;      // [8]
    int t = threadIdx.x;

    for (int j = t; j < NS; j += 256) occ[j] = LAMB * (float)g_cnt[j];
    __syncthreads();

#pragma unroll 1
    for (int r = 0; r < 8; r++) {
        int p = blockIdx.x * 8 + r;
        const uint4* drow = (const uint4*)&g_dh[(size_t)p * NS];

        float m = 3.4e38f;
        for (int j8 = t; j8 < NS / 8; j8 += 256) {
            uint4 u = drow[j8];
            const __half* h = (const __half*)&u;
            int j = j8 * 8;
            float lm = 3.4e38f;
#pragma unroll
            for (int e = 0; e < 8; e++) {
                float v = __half2float(h[e]) + occ[j + e];
                sd[j + e] = v;
                lm = fminf(lm, v);
            }
            m = fminf(m, lm);
        }
#pragma unroll
        for (int o = 16; o; o >>= 1) m = fminf(m, __shfl_xor_sync(0xffffffffu, m, o));
        if ((t & 31) == 0) sr[t >> 5] = m;
        __syncthreads();
        if (t == 0) {
            float x = sr[0];
#pragma unroll
            for (int w = 1; w < 8; w++) x = fminf(x, sr[w]);
            sr[0] = x;
        }
        __syncthreads();
        m = sr[0];
        __syncthreads();

        float meps = __fadd_rn(m, EPSF);
        float inv = 1.0f / meps;

        float s = 0.0f;
        for (int j = t; j < NS; j += 256) {
            float rr = sd[j] * inv;
            s += __expf(__fmul_rn(__fadd_rn(1.0f, -rr), 2.0f));
        }
#pragma unroll
        for (int o = 16; o; o >>= 1) s += __shfl_xor_sync(0xffffffffu, s, o);
        if ((t & 31) == 0) sr[t >> 5] = s;
        __syncthreads();
        if (t == 0) {
            float st = 0.0f;
#pragma unroll
            for (int w = 0; w < 8; w++) st += sr[w];
            float emax = __fmul_rn(__fadd_rn(1.0f, -__fmul_rn(m, inv)), 2.0f);
            g_rowloss[p] = logf(st) - emax;
        }
        __syncthreads();
    }
}

// ---------------- 7) final mean ----------------
__global__ void k_final(float* __restrict__ out) {
    int t = threadIdx.x;
    float s = 0.0f;
    for (int p = t; p < NS; p += 256) s += g_rowloss[p];
    __shared__ float sm[256];
    sm[t] = s; __syncthreads();
    for (int st = 128; st; st >>= 1) { if (t < st) sm[t] += sm[t + st]; __syncthreads(); }
    if (t == 0) out[0] = sm[0] * (1.0f / (float)NS);
}

// ---------------- host launch ----------------
extern "C" void kernel_launch(void* const* d_in, const int* in_sizes, int n_in,
                              void* d_out, int out_size) {
    (void)in_sizes; (void)n_in; (void)out_size;
    const float* timg   = (const float*)d_in[0];
    const float* rimg   = (const float*)d_in[1];
    const float* tfield = (const float*)d_in[2];
    const float* rfield = (const float*)d_in[3];
    float* out = (float*)d_out;

    const int ROW_SMEM = (2 * NS + 8) * (int)sizeof(float);          // 51232 B
    cudaFuncSetAttribute(k_gemm, cudaFuncAttributeMaxDynamicSharedMemorySize, GEMM_SMEM);
    cudaFuncSetAttribute(k_row,  cudaFuncAttributeMaxDynamicSharedMemorySize, ROW_SMEM);

    k_idx  <<<50, 256>>>(tfield, rfield);
    k_mean <<<CCH, 256>>>(rimg);
    k_feat <<<dim3(50, 2), 128>>>(timg, rimg);
    k_gemm <<<NCTA, 256, GEMM_SMEM>>>();
    k_cnt  <<<25, 256>>>();
    k_row  <<<800, 256, ROW_SMEM>>>();
    k_final<<<1, 256>>>(out);
}

// round 14
// speedup vs baseline: 1.2751x; 1.0455x over previous
#include <cuda_runtime.h>
#include <cuda_fp16.h>
#include <cuda_bf16.h>
#include <cstdint>
#include <math.h>

// ---------------- problem constants ----------------
#define NS    6400          // SAMPLE*SAMPLE patches per image
#define CCH   49            // PATCH*PATCH channels
#define IMGW  512
#define GW    169           // (512-7)/3 + 1 patch-grid size
#define EPSF  2.2204460492503131e-16f
#define LAMB  0.05f
#define KST   168           // row stride in bf16 (160 active K + 8 pad)
#define DPAD  72            // d staging row stride in halves (64 + 8 pad)
#define NTILES 5000         // 50 row bands x 100 col tiles
#define NCTA  296           // 2 CTAs x 148 SMs, one wave
#define L2E2  2.8853900817779268f   // 2*log2(e)

// ---------------- device scratch ----------------
__device__ int   g_base_t[NS];
__device__ int   g_base_r[NS];
__device__ float g_ymean[CCH];
__device__ __nv_bfloat16 g_xr[(size_t)NS * KST];  // target rows [hi49|hi49|lo49|0...]
__device__ __nv_bfloat16 g_yr[(size_t)NS * KST];  // refer  rows [hi49|lo49|hi49|0...]
__device__ __half g_dh[(size_t)NS * NS];          // 81.92 MB distance matrix (fp16)
__device__ unsigned long long g_amin[NS];
__device__ int   g_cnt[NS];
__device__ float g_rowloss[NS];

// ---------------- helpers ----------------
__device__ __forceinline__ uint32_t smem_to_u32(const void* p) {
    uint32_t a;
    asm("{ .reg .u64 t; cvta.to.shared.u64 t, %1; cvt.u32.u64 %0, t; }" : "=r"(a) : "l"(p));
    return a;
}
__device__ __forceinline__ void ldsm_x4(uint32_t& r0, uint32_t& r1, uint32_t& r2, uint32_t& r3,
                                        uint32_t addr) {
    asm volatile("ldmatrix.sync.aligned.m8n8.x4.shared.b16 {%0,%1,%2,%3}, [%4];"
                 : "=r"(r0), "=r"(r1), "=r"(r2), "=r"(r3) : "r"(addr));
}
__device__ __forceinline__ void mma16816(float* c, const uint32_t* a, const uint32_t* b) {
    asm volatile("mma.sync.aligned.m16n8k16.row.col.f32.bf16.bf16.f32 "
                 "{%0,%1,%2,%3}, {%4,%5,%6,%7}, {%8,%9}, {%0,%1,%2,%3};"
                 : "+f"(c[0]), "+f"(c[1]), "+f"(c[2]), "+f"(c[3])
                 : "r"(a[0]), "r"(a[1]), "r"(a[2]), "r"(a[3]), "r"(b[0]), "r"(b[1]));
}
__device__ __forceinline__ void cp16(uint32_t dst, const void* src) {
    asm volatile("cp.async.cg.shared.global [%0], [%1], 16;" :: "r"(dst), "l"(src));
}
#define CP_COMMIT() asm volatile("cp.async.commit_group;" ::: "memory")
#define CP_WAIT(n)  asm volatile("cp.async.wait_group %0;" :: "n"(n) : "memory")

// ---------------- 1) grid-sample nearest indices (+ init amin/cnt/ymean) ----------------
__global__ void k_idx(const float* __restrict__ tfield, const float* __restrict__ rfield) {
    int i = blockIdx.x * blockDim.x + threadIdx.x;
    if (i < NS) { g_amin[i] = ~0ull; g_cnt[i] = 0; }
    if (i < CCH) g_ymean[i] = 0.0f;
    if (i >= 2 * NS) return;
    const float* f = (i < NS) ? tfield : rfield;
    int p = (i < NS) ? i : (i - NS);
    float gx = __fadd_rn(__fmul_rn(f[2 * p + 0], 2.0f), -1.0f);
    float gy = __fadd_rn(__fmul_rn(f[2 * p + 1], 2.0f), -1.0f);
    float fx = __fmul_rn(__fadd_rn(__fmul_rn(__fadd_rn(gx, 1.0f), (float)GW), -1.0f), 0.5f);
    float fy = __fmul_rn(__fadd_rn(__fmul_rn(__fadd_rn(gy, 1.0f), (float)GW), -1.0f), 0.5f);
    int ix = (int)rintf(fx); ix = ix < 0 ? 0 : (ix > GW - 1 ? GW - 1 : ix);
    int iy = (int)rintf(fy); iy = iy < 0 ? 0 : (iy > GW - 1 ? GW - 1 : iy);
    int base = (iy * 3) * IMGW + ix * 3;
    if (i < NS) g_base_t[p] = base; else g_base_r[p] = base;
}

// ---------------- 2) refer patch channel mean: grid (49, 25), partial atomics ----------------
__global__ void k_mean(const float* __restrict__ rimg) {
    int c = blockIdx.x;
    int off = (c / 7) * IMGW + (c % 7);
    int t = threadIdx.x;
    int p = blockIdx.y * 256 + t;
    float s = rimg[g_base_r[p] + off];
#pragma unroll
    for (int o = 16; o; o >>= 1) s += __shfl_xor_sync(0xffffffffu, s, o);
    __shared__ float sw[8];
    if ((t & 31) == 0) sw[t >> 5] = s;
    __syncthreads();
    if (t == 0) {
        float x = 0.0f;
#pragma unroll
        for (int w = 0; w < 8; w++) x += sw[w];
        atomicAdd(&g_ymean[c], x * (1.0f / (float)NS));
    }
}

// ---------------- 3) features -> bf16 hi/lo split rows (smem-staged coalesced writes) ----------------
// X row: [hi(49) | hi(49) | lo(49) | 0] ; Y row: [hi(49) | lo(49) | hi(49) | 0]
// X.Y = hi.hi + hi.lo + lo.hi  (drops only lo.lo ~2^-18)
__global__ void __launch_bounds__(128) k_feat(const float* __restrict__ timg,
                                              const float* __restrict__ rimg) {
    __shared__ __nv_bfloat16 srow[128 * KST];   // 43008 B
    int t = threadIdx.x;
    int p = blockIdx.x * 128 + t;               // gridDim.x = 50
    bool is_t = (blockIdx.y == 0);
    const float* img = is_t ? timg : rimg;
    int base = is_t ? g_base_t[p] : g_base_r[p];

    float v[CCH];
    float sq = 0.0f;
#pragma unroll
    for (int c = 0; c < CCH; c++) {
        v[c] = img[base + (c / 7) * IMGW + (c % 7)] - g_ymean[c];
        sq += v[c] * v[c];
    }
    float inv = 1.0f / (sqrtf(sq) + EPSF);
    __nv_bfloat16* row = &srow[t * KST];
#pragma unroll
    for (int c = 0; c < CCH; c++) {
        float val = v[c] * inv;
        __nv_bfloat16 hi = __float2bfloat16(val);
        __nv_bfloat16 lo = __float2bfloat16(val - __bfloat162float(hi));
        if (is_t) { row[c] = hi; row[49 + c] = hi; row[98 + c] = lo; }
        else      { row[c] = hi; row[49 + c] = lo; row[98 + c] = hi; }
    }
    for (int k = 147; k < KST; k++) row[k] = __float2bfloat16(0.0f);
    __syncthreads();

    uint4* dst = (uint4*)((is_t ? g_xr : g_yr) + (size_t)(blockIdx.x * 128) * KST);
    const uint4* src = (const uint4*)srow;
    for (int i = t; i < 128 * 21; i += 128) dst[i] = src[i];
}

// ---------------- 4) balanced persistent tensor GEMM (unchanged from R13) ----------------
#define SM_Y0   (128 * KST * 2)
#define SM_Y1   (192 * KST * 2)
#define SM_DS   (256 * KST * 2)
#define GEMM_SMEM (SM_DS + 128 * DPAD * 2)

__global__ void __launch_bounds__(256, 2) k_gemm() {
    extern __shared__ char smem[];
    uint32_t xs_u = smem_to_u32(smem);
    uint32_t y_u0 = xs_u + SM_Y0, y_u1 = xs_u + SM_Y1;
    __half* Ds = (__half*)(smem + SM_DS);
    int t = threadIdx.x, wid = t >> 5, lid = t & 31;
    int cta = blockIdx.x;
    int ts = (cta * NTILES) / NCTA;
    int te = ((cta + 1) * NTILES) / NCTA;
    int n = te - ts;                      // 16 or 17
    int cur_band = ts / 100;

    {
        const char* xsrc = (const char*)&g_xr[(size_t)(cur_band * 128) * KST];
        for (int i = t; i < 2688; i += 256) cp16(xs_u + i * 16, xsrc + (size_t)i * 16);
        const char* y0 = (const char*)&g_yr[(size_t)((ts % 100) * 64) * KST];
        for (int i = t; i < 1344; i += 256) cp16(y_u0 + i * 16, y0 + (size_t)i * 16);
        CP_COMMIT();
        if (n > 1) {
            const char* y1 = (const char*)&g_yr[(size_t)(((ts + 1) % 100) * 64) * KST];
            for (int i = t; i < 1344; i += 256) cp16(y_u1 + i * 16, y1 + (size_t)i * 16);
        }
        CP_COMMIT();
    }
    CP_WAIT(1);
    __syncthreads();

    int MR = (wid & 3) * 32, NC = (wid >> 2) * 32;
    int arow = (lid & 7) + ((lid >> 3) & 1) * 8;
    int akof = (lid >> 4) * 8;
    int brow = (lid & 7) + ((lid >> 4) & 1) * 8;
    int bkof = ((lid >> 3) & 1) * 8;
    int g = lid >> 2, tq = lid & 3;

    for (int it = 0; it < n; it++) {
        int tile = ts + it;
        int band = tile / 100, col = tile % 100;
        uint32_t yb = (it & 1) ? y_u1 : y_u0;

        if (band != cur_band) {           // <=1 time per CTA
            CP_WAIT(0);
            __syncthreads();
            const char* xsrc = (const char*)&g_xr[(size_t)(band * 128) * KST];
            for (int i = t; i < 2688; i += 256) cp16(xs_u + i * 16, xsrc + (size_t)i * 16);
            CP_COMMIT();
            CP_WAIT(0);
            __syncthreads();
            cur_band = band;
        }

        float acc[2][4][4];
#pragma unroll
        for (int i = 0; i < 2; i++)
#pragma unroll
            for (int j = 0; j < 4; j++)
#pragma unroll
                for (int e = 0; e < 4; e++) acc[i][j][e] = 0.0f;

#pragma unroll
        for (int k = 0; k < 10; k++) {
            int kb = k * 16;
            uint32_t a[2][4];
#pragma unroll
            for (int mt = 0; mt < 2; mt++)
                ldsm_x4(a[mt][0], a[mt][1], a[mt][2], a[mt][3],
                        xs_u + ((MR + mt * 16 + arow) * KST + kb + akof) * 2);
            uint32_t b[4][2];
#pragma unroll
            for (int nt2 = 0; nt2 < 2; nt2++)
                ldsm_x4(b[2 * nt2][0], b[2 * nt2][1], b[2 * nt2 + 1][0], b[2 * nt2 + 1][1],
                        yb + ((NC + nt2 * 16 + brow) * KST + kb + bkof) * 2);
#pragma unroll
            for (int mt = 0; mt < 2; mt++)
#pragma unroll
                for (int nt = 0; nt < 4; nt++)
                    mma16816(acc[mt][nt], a[mt], b[nt]);
        }

#pragma unroll
        for (int mt = 0; mt < 2; mt++) {
            int rl0 = MR + mt * 16 + g;
            int rl1 = rl0 + 8;
            float v0 = 1e30f, v1 = 1e30f;
            int i0 = 0, i1 = 0;
#pragma unroll
            for (int nt = 0; nt < 4; nt++) {
                int cl = NC + nt * 8 + tq * 2;
                int gcol = col * 64 + cl;
                float d00 = fmaxf(fmaf(acc[mt][nt][0], -0.5f, 0.5f), 0.0f);
                float d01 = fmaxf(fmaf(acc[mt][nt][1], -0.5f, 0.5f), 0.0f);
                float d10 = fmaxf(fmaf(acc[mt][nt][2], -0.5f, 0.5f), 0.0f);
                float d11 = fmaxf(fmaf(acc[mt][nt][3], -0.5f, 0.5f), 0.0f);
                uint32_t p0, p1;
                asm("cvt.rn.f16x2.f32 %0, %1, %2;" : "=r"(p0) : "f"(d01), "f"(d00));
                asm("cvt.rn.f16x2.f32 %0, %1, %2;" : "=r"(p1) : "f"(d11), "f"(d10));
                *(uint32_t*)&Ds[rl0 * DPAD + cl] = p0;
                *(uint32_t*)&Ds[rl1 * DPAD + cl] = p1;
                if (d00 < v0) { v0 = d00; i0 = gcol; }
                if (d01 < v0) { v0 = d01; i0 = gcol + 1; }
                if (d10 < v1) { v1 = d10; i1 = gcol; }
                if (d11 < v1) { v1 = d11; i1 = gcol + 1; }
            }
#pragma unroll
            for (int o = 1; o < 4; o <<= 1) {
                float vo0 = __shfl_xor_sync(0xffffffffu, v0, o);
                int   io0 = __shfl_xor_sync(0xffffffffu, i0, o);
                if (vo0 < v0 || (vo0 == v0 && io0 < i0)) { v0 = vo0; i0 = io0; }
                float vo1 = __shfl_xor_sync(0xffffffffu, v1, o);
                int   io1 = __shfl_xor_sync(0xffffffffu, i1, o);
                if (vo1 < v1 || (vo1 == v1 && io1 < i1)) { v1 = vo1; i1 = io1; }
            }
            if (tq == 0) {
                atomicMin(&g_amin[band * 128 + rl0],
                          ((unsigned long long)__float_as_uint(v0) << 32) | (unsigned)i0);
                atomicMin(&g_amin[band * 128 + rl1],
                          ((unsigned long long)__float_as_uint(v1) << 32) | (unsigned)i1);
            }
        }
        __syncthreads();

        if (it + 2 < n) {
            int coln = (tile + 2) % 100;
            const char* ysrc = (const char*)&g_yr[(size_t)(coln * 64) * KST];
            for (int i = t; i < 1344; i += 256) cp16(yb + i * 16, ysrc + (size_t)i * 16);
        }
        CP_COMMIT();

        for (int i = t; i < 1024; i += 256) {
            int row = i >> 3, c8 = i & 7;
            *(uint4*)&g_dh[(size_t)(cur_band * 128 + row) * NS + col * 64 + c8 * 8] =
                *(const uint4*)&Ds[row * DPAD + c8 * 8];
        }

        CP_WAIT(1);
        __syncthreads();
    }
}

// ---------------- 5) occurrence counts ----------------
__global__ void k_cnt() {
    int p = blockIdx.x * 256 + threadIdx.x;
    if (p < NS) {
        unsigned q = (unsigned)(g_amin[p] & 0xffffffffu);
        atomicAdd(&g_cnt[q], 1);
    }
}

// ---------------- 6) per-row min + sum-exp -> row loss (8 rows per block) ----------------
__global__ void __launch_bounds__(256) k_row() {
    extern __shared__ float dyn[];
    float* occ = dyn;               // [NS]
    float* sd  = dyn + NS;          // [NS]
    float* sr  = dyn + 2 * NS;      // [8]
    int t = threadIdx.x;

    for (int j = t; j < NS; j += 256) occ[j] = LAMB * (float)g_cnt[j];
    __syncthreads();

#pragma unroll 1
    for (int r = 0; r < 8; r++) {
        int p = blockIdx.x * 8 + r;
        const uint4* drow = (const uint4*)&g_dh[(size_t)p * NS];

        // pass 1: load + occurrence add + min, vectorized stores
        float m = 3.4e38f;
        for (int j8 = t; j8 < NS / 8; j8 += 256) {
            uint4 u = drow[j8];
            const __half2* h2 = (const __half2*)&u;
            int j = j8 * 8;
            float4 o0 = *(const float4*)&occ[j];
            float4 o1 = *(const float4*)&occ[j + 4];
            float2 a0 = __half22float2(h2[0]);
            float2 a1 = __half22float2(h2[1]);
            float2 a2 = __half22float2(h2[2]);
            float2 a3 = __half22float2(h2[3]);
            float4 f0 = make_float4(a0.x + o0.x, a0.y + o0.y, a1.x + o0.z, a1.y + o0.w);
            float4 f1 = make_float4(a2.x + o1.x, a2.y + o1.y, a3.x + o1.z, a3.y + o1.w);
            *(float4*)&sd[j]     = f0;
            *(float4*)&sd[j + 4] = f1;
            float m0 = fminf(fminf(f0.x, f0.y), fminf(f0.z, f0.w));
            float m1 = fminf(fminf(f1.x, f1.y), fminf(f1.z, f1.w));
            m = fminf(m, fminf(m0, m1));
        }
#pragma unroll
        for (int o = 16; o; o >>= 1) m = fminf(m, __shfl_xor_sync(0xffffffffu, m, o));
        if ((t & 31) == 0) sr[t >> 5] = m;
        __syncthreads();
        if (t == 0) {
            float x = sr[0];
#pragma unroll
            for (int w = 1; w < 8; w++) x = fminf(x, sr[w]);
            sr[0] = x;
        }
        __syncthreads();
        m = sr[0];
        __syncthreads();

        float meps = __fadd_rn(m, EPSF);
        float inv = 1.0f / meps;
        float nb = -L2E2 * inv;     // exponent(base2) = L2E2 + sd * nb  ==  (1 - sd*inv)*2*log2e

        // pass 2: sum of w = exp2(L2E2 + sd*nb)
        float s = 0.0f;
        for (int j = t; j < NS; j += 256)
            s += exp2f(fmaf(sd[j], nb, L2E2));
#pragma unroll
        for (int o = 16; o; o >>= 1) s += __shfl_xor_sync(0xffffffffu, s, o);
        if ((t & 31) == 0) sr[t >> 5] = s;
        __syncthreads();
        if (t == 0) {
            float st = 0.0f;
#pragma unroll
            for (int w = 0; w < 8; w++) st += sr[w];
            float emax = __fmul_rn(__fadd_rn(1.0f, -__fmul_rn(m, inv)), 2.0f);
            g_rowloss[p] = logf(st) - emax;
        }
        __syncthreads();
    }
}

// ---------------- 7) final mean ----------------
__global__ void k_final(float* __restrict__ out) {
    int t = threadIdx.x;
    float s = 0.0f;
    for (int p = t; p < NS; p += 256) s += g_rowloss[p];
    __shared__ float sm[256];
    sm[t] = s; __syncthreads();
    for (int st = 128; st; st >>= 1) { if (t < st) sm[t] += sm[t + st]; __syncthreads(); }
    if (t == 0) out[0] = sm[0] * (1.0f / (float)NS);
}

// ---------------- host launch ----------------
extern "C" void kernel_launch(void* const* d_in, const int* in_sizes, int n_in,
                              void* d_out, int out_size) {
    (void)in_sizes; (void)n_in; (void)out_size;
    const float* timg   = (const float*)d_in[0];
    const float* rimg   = (const float*)d_in[1];
    const float* tfield = (const float*)d_in[2];
    const float* rfield = (const float*)d_in[3];
    float* out = (float*)d_out;

    const int ROW_SMEM = (2 * NS + 8) * (int)sizeof(float);          // 51232 B
    cudaFuncSetAttribute(k_gemm, cudaFuncAttributeMaxDynamicSharedMemorySize, GEMM_SMEM);
    cudaFuncSetAttribute(k_row,  cudaFuncAttributeMaxDynamicSharedMemorySize, ROW_SMEM);

    k_idx  <<<50, 256>>>(tfield, rfield);
    k_mean <<<dim3(CCH, 25), 256>>>(rimg);
    k_feat <<<dim3(50, 2), 128>>>(timg, rimg);
    k_gemm <<<NCTA, 256, GEMM_SMEM>>>();
    k_cnt  <<<25, 256>>>();
    k_row  <<<800, 256, ROW_SMEM>>>();
    k_final<<<1, 256>>>(out);
}

// round 15
// speedup vs baseline: 1.4026x; 1.1000x over previous
#include <cuda_runtime.h>
#include <cuda_fp16.h>
#include <cuda_bf16.h>
#include <cstdint>
#include <math.h>

// ---------------- problem constants ----------------
#define NS    6400          // SAMPLE*SAMPLE patches per image
#define CCH   49            // PATCH*PATCH channels
#define IMGW  512
#define GW    169           // (512-7)/3 + 1 patch-grid size
#define EPSF  2.2204460492503131e-16f
#define LAMB  0.05f
#define KST   168           // row stride in bf16 (160 active K + 8 pad)
#define DPAD  72            // d staging row stride in halves (64 + 8 pad)
#define NTILES 5000         // 50 row bands x 100 col tiles
#define NCTA  296           // 2 CTAs x 148 SMs, one wave
#define NROWCTA 592         // 4 CTAs x 148 SMs, one wave (k_row)
#define L2E2  2.8853900817779268f   // 2*log2(e)

// ---------------- device scratch ----------------
__device__ int   g_base_t[NS];
__device__ int   g_base_r[NS];
__device__ float g_ymean[CCH];
__device__ __nv_bfloat16 g_xr[(size_t)NS * KST];  // target rows [hi49|hi49|lo49|0...]
__device__ __nv_bfloat16 g_yr[(size_t)NS * KST];  // refer  rows [hi49|lo49|hi49|0...]
__device__ __half g_dh[(size_t)NS * NS];          // 81.92 MB distance matrix (fp16)
__device__ unsigned long long g_amin[NS];
__device__ int   g_cnt[NS];
__device__ float g_rowloss[NS];

// ---------------- helpers ----------------
__device__ __forceinline__ uint32_t smem_to_u32(const void* p) {
    uint32_t a;
    asm("{ .reg .u64 t; cvta.to.shared.u64 t, %1; cvt.u32.u64 %0, t; }" : "=r"(a) : "l"(p));
    return a;
}
__device__ __forceinline__ void ldsm_x4(uint32_t& r0, uint32_t& r1, uint32_t& r2, uint32_t& r3,
                                        uint32_t addr) {
    asm volatile("ldmatrix.sync.aligned.m8n8.x4.shared.b16 {%0,%1,%2,%3}, [%4];"
                 : "=r"(r0), "=r"(r1), "=r"(r2), "=r"(r3) : "r"(addr));
}
__device__ __forceinline__ void mma16816(float* c, const uint32_t* a, const uint32_t* b) {
    asm volatile("mma.sync.aligned.m16n8k16.row.col.f32.bf16.bf16.f32 "
                 "{%0,%1,%2,%3}, {%4,%5,%6,%7}, {%8,%9}, {%0,%1,%2,%3};"
                 : "+f"(c[0]), "+f"(c[1]), "+f"(c[2]), "+f"(c[3])
                 : "r"(a[0]), "r"(a[1]), "r"(a[2]), "r"(a[3]), "r"(b[0]), "r"(b[1]));
}
__device__ __forceinline__ void cp16(uint32_t dst, const void* src) {
    asm volatile("cp.async.cg.shared.global [%0], [%1], 16;" :: "r"(dst), "l"(src));
}
#define CP_COMMIT() asm volatile("cp.async.commit_group;" ::: "memory")
#define CP_WAIT(n)  asm volatile("cp.async.wait_group %0;" :: "n"(n) : "memory")

// ---------------- 1) grid-sample nearest indices (+ init amin/cnt/ymean) ----------------
__global__ void k_idx(const float* __restrict__ tfield, const float* __restrict__ rfield) {
    int i = blockIdx.x * blockDim.x + threadIdx.x;
    if (i < NS) { g_amin[i] = ~0ull; g_cnt[i] = 0; }
    if (i < CCH) g_ymean[i] = 0.0f;
    if (i >= 2 * NS) return;
    const float* f = (i < NS) ? tfield : rfield;
    int p = (i < NS) ? i : (i - NS);
    float gx = __fadd_rn(__fmul_rn(f[2 * p + 0], 2.0f), -1.0f);
    float gy = __fadd_rn(__fmul_rn(f[2 * p + 1], 2.0f), -1.0f);
    float fx = __fmul_rn(__fadd_rn(__fmul_rn(__fadd_rn(gx, 1.0f), (float)GW), -1.0f), 0.5f);
    float fy = __fmul_rn(__fadd_rn(__fmul_rn(__fadd_rn(gy, 1.0f), (float)GW), -1.0f), 0.5f);
    int ix = (int)rintf(fx); ix = ix < 0 ? 0 : (ix > GW - 1 ? GW - 1 : ix);
    int iy = (int)rintf(fy); iy = iy < 0 ? 0 : (iy > GW - 1 ? GW - 1 : iy);
    int base = (iy * 3) * IMGW + ix * 3;
    if (i < NS) g_base_t[p] = base; else g_base_r[p] = base;
}

// ---------------- 2) refer patch channel mean: grid (49, 25), partial atomics ----------------
__global__ void k_mean(const float* __restrict__ rimg) {
    int c = blockIdx.x;
    int off = (c / 7) * IMGW + (c % 7);
    int t = threadIdx.x;
    int p = blockIdx.y * 256 + t;
    float s = rimg[g_base_r[p] + off];
#pragma unroll
    for (int o = 16; o; o >>= 1) s += __shfl_xor_sync(0xffffffffu, s, o);
    __shared__ float sw[8];
    if ((t & 31) == 0) sw[t >> 5] = s;
    __syncthreads();
    if (t == 0) {
        float x = 0.0f;
#pragma unroll
        for (int w = 0; w < 8; w++) x += sw[w];
        atomicAdd(&g_ymean[c], x * (1.0f / (float)NS));
    }
}

// ---------------- 3) features -> bf16 hi/lo split rows (smem-staged coalesced writes) ----------------
__global__ void __launch_bounds__(128) k_feat(const float* __restrict__ timg,
                                              const float* __restrict__ rimg) {
    __shared__ __nv_bfloat16 srow[128 * KST];   // 43008 B
    int t = threadIdx.x;
    int p = blockIdx.x * 128 + t;               // gridDim.x = 50
    bool is_t = (blockIdx.y == 0);
    const float* img = is_t ? timg : rimg;
    int base = is_t ? g_base_t[p] : g_base_r[p];

    float v[CCH];
    float sq = 0.0f;
#pragma unroll
    for (int c = 0; c < CCH; c++) {
        v[c] = img[base + (c / 7) * IMGW + (c % 7)] - g_ymean[c];
        sq += v[c] * v[c];
    }
    float inv = 1.0f / (sqrtf(sq) + EPSF);
    __nv_bfloat16* row = &srow[t * KST];
#pragma unroll
    for (int c = 0; c < CCH; c++) {
        float val = v[c] * inv;
        __nv_bfloat16 hi = __float2bfloat16(val);
        __nv_bfloat16 lo = __float2bfloat16(val - __bfloat162float(hi));
        if (is_t) { row[c] = hi; row[49 + c] = hi; row[98 + c] = lo; }
        else      { row[c] = hi; row[49 + c] = lo; row[98 + c] = hi; }
    }
    for (int k = 147; k < KST; k++) row[k] = __float2bfloat16(0.0f);
    __syncthreads();

    uint4* dst = (uint4*)((is_t ? g_xr : g_yr) + (size_t)(blockIdx.x * 128) * KST);
    const uint4* src = (const uint4*)srow;
    for (int i = t; i < 128 * 21; i += 128) dst[i] = src[i];
}

// ---------------- 4) balanced persistent tensor GEMM (unchanged from R13) ----------------
#define SM_Y0   (128 * KST * 2)
#define SM_Y1   (192 * KST * 2)
#define SM_DS   (256 * KST * 2)
#define GEMM_SMEM (SM_DS + 128 * DPAD * 2)

__global__ void __launch_bounds__(256, 2) k_gemm() {
    extern __shared__ char smem[];
    uint32_t xs_u = smem_to_u32(smem);
    uint32_t y_u0 = xs_u + SM_Y0, y_u1 = xs_u + SM_Y1;
    __half* Ds = (__half*)(smem + SM_DS);
    int t = threadIdx.x, wid = t >> 5, lid = t & 31;
    int cta = blockIdx.x;
    int ts = (cta * NTILES) / NCTA;
    int te = ((cta + 1) * NTILES) / NCTA;
    int n = te - ts;                      // 16 or 17
    int cur_band = ts / 100;

    {
        const char* xsrc = (const char*)&g_xr[(size_t)(cur_band * 128) * KST];
        for (int i = t; i < 2688; i += 256) cp16(xs_u + i * 16, xsrc + (size_t)i * 16);
        const char* y0 = (const char*)&g_yr[(size_t)((ts % 100) * 64) * KST];
        for (int i = t; i < 1344; i += 256) cp16(y_u0 + i * 16, y0 + (size_t)i * 16);
        CP_COMMIT();
        if (n > 1) {
            const char* y1 = (const char*)&g_yr[(size_t)(((ts + 1) % 100) * 64) * KST];
            for (int i = t; i < 1344; i += 256) cp16(y_u1 + i * 16, y1 + (size_t)i * 16);
        }
        CP_COMMIT();
    }
    CP_WAIT(1);
    __syncthreads();

    int MR = (wid & 3) * 32, NC = (wid >> 2) * 32;
    int arow = (lid & 7) + ((lid >> 3) & 1) * 8;
    int akof = (lid >> 4) * 8;
    int brow = (lid & 7) + ((lid >> 4) & 1) * 8;
    int bkof = ((lid >> 3) & 1) * 8;
    int g = lid >> 2, tq = lid & 3;

    for (int it = 0; it < n; it++) {
        int tile = ts + it;
        int band = tile / 100, col = tile % 100;
        uint32_t yb = (it & 1) ? y_u1 : y_u0;

        if (band != cur_band) {           // <=1 time per CTA
            CP_WAIT(0);
            __syncthreads();
            const char* xsrc = (const char*)&g_xr[(size_t)(band * 128) * KST];
            for (int i = t; i < 2688; i += 256) cp16(xs_u + i * 16, xsrc + (size_t)i * 16);
            CP_COMMIT();
            CP_WAIT(0);
            __syncthreads();
            cur_band = band;
        }

        float acc[2][4][4];
#pragma unroll
        for (int i = 0; i < 2; i++)
#pragma unroll
            for (int j = 0; j < 4; j++)
#pragma unroll
                for (int e = 0; e < 4; e++) acc[i][j][e] = 0.0f;

#pragma unroll
        for (int k = 0; k < 10; k++) {
            int kb = k * 16;
            uint32_t a[2][4];
#pragma unroll
            for (int mt = 0; mt < 2; mt++)
                ldsm_x4(a[mt][0], a[mt][1], a[mt][2], a[mt][3],
                        xs_u + ((MR + mt * 16 + arow) * KST + kb + akof) * 2);
            uint32_t b[4][2];
#pragma unroll
            for (int nt2 = 0; nt2 < 2; nt2++)
                ldsm_x4(b[2 * nt2][0], b[2 * nt2][1], b[2 * nt2 + 1][0], b[2 * nt2 + 1][1],
                        yb + ((NC + nt2 * 16 + brow) * KST + kb + bkof) * 2);
#pragma unroll
            for (int mt = 0; mt < 2; mt++)
#pragma unroll
                for (int nt = 0; nt < 4; nt++)
                    mma16816(acc[mt][nt], a[mt], b[nt]);
        }

#pragma unroll
        for (int mt = 0; mt < 2; mt++) {
            int rl0 = MR + mt * 16 + g;
            int rl1 = rl0 + 8;
            float v0 = 1e30f, v1 = 1e30f;
            int i0 = 0, i1 = 0;
#pragma unroll
            for (int nt = 0; nt < 4; nt++) {
                int cl = NC + nt * 8 + tq * 2;
                int gcol = col * 64 + cl;
                float d00 = fmaxf(fmaf(acc[mt][nt][0], -0.5f, 0.5f), 0.0f);
                float d01 = fmaxf(fmaf(acc[mt][nt][1], -0.5f, 0.5f), 0.0f);
                float d10 = fmaxf(fmaf(acc[mt][nt][2], -0.5f, 0.5f), 0.0f);
                float d11 = fmaxf(fmaf(acc[mt][nt][3], -0.5f, 0.5f), 0.0f);
                uint32_t p0, p1;
                asm("cvt.rn.f16x2.f32 %0, %1, %2;" : "=r"(p0) : "f"(d01), "f"(d00));
                asm("cvt.rn.f16x2.f32 %0, %1, %2;" : "=r"(p1) : "f"(d11), "f"(d10));
                *(uint32_t*)&Ds[rl0 * DPAD + cl] = p0;
                *(uint32_t*)&Ds[rl1 * DPAD + cl] = p1;
                if (d00 < v0) { v0 = d00; i0 = gcol; }
                if (d01 < v0) { v0 = d01; i0 = gcol + 1; }
                if (d10 < v1) { v1 = d10; i1 = gcol; }
                if (d11 < v1) { v1 = d11; i1 = gcol + 1; }
            }
#pragma unroll
            for (int o = 1; o < 4; o <<= 1) {
                float vo0 = __shfl_xor_sync(0xffffffffu, v0, o);
                int   io0 = __shfl_xor_sync(0xffffffffu, i0, o);
                if (vo0 < v0 || (vo0 == v0 && io0 < i0)) { v0 = vo0; i0 = io0; }
                float vo1 = __shfl_xor_sync(0xffffffffu, v1, o);
                int   io1 = __shfl_xor_sync(0xffffffffu, i1, o);
                if (vo1 < v1 || (vo1 == v1 && io1 < i1)) { v1 = vo1; i1 = io1; }
            }
            if (tq == 0) {
                atomicMin(&g_amin[cur_band * 128 + rl0],
                          ((unsigned long long)__float_as_uint(v0) << 32) | (unsigned)i0);
                atomicMin(&g_amin[cur_band * 128 + rl1],
                          ((unsigned long long)__float_as_uint(v1) << 32) | (unsigned)i1);
            }
        }
        __syncthreads();

        if (it + 2 < n) {
            int coln = (tile + 2) % 100;
            const char* ysrc = (const char*)&g_yr[(size_t)(coln * 64) * KST];
            for (int i = t; i < 1344; i += 256) cp16(yb + i * 16, ysrc + (size_t)i * 16);
        }
        CP_COMMIT();

        for (int i = t; i < 1024; i += 256) {
            int row = i >> 3, c8 = i & 7;
            *(uint4*)&g_dh[(size_t)(cur_band * 128 + row) * NS + col * 64 + c8 * 8] =
                *(const uint4*)&Ds[row * DPAD + c8 * 8];
        }

        CP_WAIT(1);
        __syncthreads();
    }
}

// ---------------- 5) occurrence counts ----------------
__global__ void k_cnt() {
    int p = blockIdx.x * 256 + threadIdx.x;
    if (p < NS) {
        unsigned q = (unsigned)(g_amin[p] & 0xffffffffu);
        atomicAdd(&g_cnt[q], 1);
    }
}

// ---------------- 6) per-row min + sum-exp -> row loss (balanced ranges, 1 wave) ----------------
// grid NROWCTA=592 blocks; block b owns rows [b*NS/592, (b+1)*NS/592) (10 or 11 rows)
__global__ void __launch_bounds__(256) k_row() {
    extern __shared__ float dyn[];
    float* occ = dyn;               // [NS]
    float* sd  = dyn + NS;          // [NS]
    float* sr  = dyn + 2 * NS;      // [8]
    int t = threadIdx.x;
    int rs = (blockIdx.x * NS) / NROWCTA;
    int re = ((blockIdx.x + 1) * NS) / NROWCTA;

    for (int j = t; j < NS; j += 256) occ[j] = LAMB * (float)g_cnt[j];
    __syncthreads();

#pragma unroll 1
    for (int p = rs; p < re; p++) {
        const uint4* drow = (const uint4*)&g_dh[(size_t)p * NS];

        // pass 1: load + occurrence add + min, vectorized stores
        float m = 3.4e38f;
        for (int j8 = t; j8 < NS / 8; j8 += 256) {
            uint4 u = drow[j8];
            const __half2* h2 = (const __half2*)&u;
            int j = j8 * 8;
            float4 o0 = *(const float4*)&occ[j];
            float4 o1 = *(const float4*)&occ[j + 4];
            float2 a0 = __half22float2(h2[0]);
            float2 a1 = __half22float2(h2[1]);
            float2 a2 = __half22float2(h2[2]);
            float2 a3 = __half22float2(h2[3]);
            float4 f0 = make_float4(a0.x + o0.x, a0.y + o0.y, a1.x + o0.z, a1.y + o0.w);
            float4 f1 = make_float4(a2.x + o1.x, a2.y + o1.y, a3.x + o1.z, a3.y + o1.w);
            *(float4*)&sd[j]     = f0;
            *(float4*)&sd[j + 4] = f1;
            float m0 = fminf(fminf(f0.x, f0.y), fminf(f0.z, f0.w));
            float m1 = fminf(fminf(f1.x, f1.y), fminf(f1.z, f1.w));
            m = fminf(m, fminf(m0, m1));
        }
#pragma unroll
        for (int o = 16; o; o >>= 1) m = fminf(m, __shfl_xor_sync(0xffffffffu, m, o));
        if ((t & 31) == 0) sr[t >> 5] = m;
        __syncthreads();
        if (t == 0) {
            float x = sr[0];
#pragma unroll
            for (int w = 1; w < 8; w++) x = fminf(x, sr[w]);
            sr[0] = x;
        }
        __syncthreads();
        m = sr[0];
        __syncthreads();

        float meps = __fadd_rn(m, EPSF);
        float inv = 1.0f / meps;
        float nb = -L2E2 * inv;     // exponent(base2) = L2E2 + sd * nb

        // pass 2: sum of w = exp2(L2E2 + sd*nb)
        float s = 0.0f;
        for (int j = t; j < NS; j += 256)
            s += exp2f(fmaf(sd[j], nb, L2E2));
#pragma unroll
        for (int o = 16; o; o >>= 1) s += __shfl_xor_sync(0xffffffffu, s, o);
        if ((t & 31) == 0) sr[t >> 5] = s;
        __syncthreads();
        if (t == 0) {
            float st = 0.0f;
#pragma unroll
            for (int w = 0; w < 8; w++) st += sr[w];
            float emax = __fmul_rn(__fadd_rn(1.0f, -__fmul_rn(m, inv)), 2.0f);
            g_rowloss[p] = logf(st) - emax;
        }
        __syncthreads();
    }
}

// ---------------- 7) final mean ----------------
__global__ void k_final(float* __restrict__ out) {
    int t = threadIdx.x;
    float s = 0.0f;
    for (int p = t; p < NS; p += 256) s += g_rowloss[p];
    __shared__ float sm[256];
    sm[t] = s; __syncthreads();
    for (int st = 128; st; st >>= 1) { if (t < st) sm[t] += sm[t + st]; __syncthreads(); }
    if (t == 0) out[0] = sm[0] * (1.0f / (float)NS);
}

// ---------------- host launch ----------------
extern "C" void kernel_launch(void* const* d_in, const int* in_sizes, int n_in,
                              void* d_out, int out_size) {
    (void)in_sizes; (void)n_in; (void)out_size;
    const float* timg   = (const float*)d_in[0];
    const float* rimg   = (const float*)d_in[1];
    const float* tfield = (const float*)d_in[2];
    const float* rfield = (const float*)d_in[3];
    float* out = (float*)d_out;

    const int ROW_SMEM = (2 * NS + 8) * (int)sizeof(float);          // 51232 B
    cudaFuncSetAttribute(k_gemm, cudaFuncAttributeMaxDynamicSharedMemorySize, GEMM_SMEM);
    cudaFuncSetAttribute(k_row,  cudaFuncAttributeMaxDynamicSharedMemorySize, ROW_SMEM);

    k_idx  <<<50, 256>>>(tfield, rfield);
    k_mean <<<dim3(CCH, 25), 256>>>(rimg);
    k_feat <<<dim3(50, 2), 128>>>(timg, rimg);
    k_gemm <<<NCTA, 256, GEMM_SMEM>>>();
    k_cnt  <<<25, 256>>>();
    k_row  <<<NROWCTA, 256, ROW_SMEM>>>();
    k_final<<<1, 256>>>(out);
}

// round 16
// speedup vs baseline: 1.4502x; 1.0339x over previous
#include <cuda_runtime.h>
#include <cuda_fp16.h>
#include <cuda_bf16.h>
#include <cstdint>
#include <math.h>

// ---------------- problem constants ----------------
#define NS    6400          // SAMPLE*SAMPLE patches per image
#define CCH   49            // PATCH*PATCH channels
#define IMGW  512
#define GW    169           // (512-7)/3 + 1 patch-grid size
#define EPSF  2.2204460492503131e-16f
#define LAMB  0.05f
#define KST   168           // row stride in bf16 (160 active K + 8 pad)
#define DPAD  72            // d staging row stride in halves (64 + 8 pad)
#define NTILES 5000         // 50 row bands x 100 col tiles
#define NCTA  296           // 2 CTAs x 148 SMs, one wave
#define NROWCTA 592         // 4 CTAs x 148 SMs, one wave (k_row)
#define L2E2  2.8853900817779268f   // 2*log2(e)

// ---------------- device scratch ----------------
__device__ int   g_base_t[NS];
__device__ int   g_base_r[NS];
__device__ float g_ymean[CCH];
__device__ __nv_bfloat16 g_xr[(size_t)NS * KST];  // target rows [hi49|hi49|lo49|0...]
__device__ __nv_bfloat16 g_yr[(size_t)NS * KST];  // refer  rows [hi49|lo49|hi49|0...]
__device__ __half g_dh[(size_t)NS * NS];          // 81.92 MB distance matrix (fp16)
__device__ unsigned long long g_amin[NS];
__device__ int   g_cnt[NS];
__device__ float g_rowloss[NS];

// ---------------- helpers ----------------
__device__ __forceinline__ uint32_t smem_to_u32(const void* p) {
    uint32_t a;
    asm("{ .reg .u64 t; cvta.to.shared.u64 t, %1; cvt.u32.u64 %0, t; }" : "=r"(a) : "l"(p));
    return a;
}
__device__ __forceinline__ void ldsm_x4(uint32_t& r0, uint32_t& r1, uint32_t& r2, uint32_t& r3,
                                        uint32_t addr) {
    asm volatile("ldmatrix.sync.aligned.m8n8.x4.shared.b16 {%0,%1,%2,%3}, [%4];"
                 : "=r"(r0), "=r"(r1), "=r"(r2), "=r"(r3) : "r"(addr));
}
__device__ __forceinline__ void mma16816(float* c, const uint32_t* a, const uint32_t* b) {
    asm volatile("mma.sync.aligned.m16n8k16.row.col.f32.bf16.bf16.f32 "
                 "{%0,%1,%2,%3}, {%4,%5,%6,%7}, {%8,%9}, {%0,%1,%2,%3};"
                 : "+f"(c[0]), "+f"(c[1]), "+f"(c[2]), "+f"(c[3])
                 : "r"(a[0]), "r"(a[1]), "r"(a[2]), "r"(a[3]), "r"(b[0]), "r"(b[1]));
}
__device__ __forceinline__ void cp16(uint32_t dst, const void* src) {
    asm volatile("cp.async.cg.shared.global [%0], [%1], 16;" :: "r"(dst), "l"(src));
}
#define CP_COMMIT() asm volatile("cp.async.commit_group;" ::: "memory")
#define CP_WAIT(n)  asm volatile("cp.async.wait_group %0;" :: "n"(n) : "memory")

// ---------------- 1) grid-sample nearest indices (+ init amin/cnt/ymean) ----------------
__global__ void k_idx(const float* __restrict__ tfield, const float* __restrict__ rfield) {
    int i = blockIdx.x * blockDim.x + threadIdx.x;
    if (i < NS) { g_amin[i] = ~0ull; g_cnt[i] = 0; }
    if (i < CCH) g_ymean[i] = 0.0f;
    if (i >= 2 * NS) return;
    const float* f = (i < NS) ? tfield : rfield;
    int p = (i < NS) ? i : (i - NS);
    float gx = __fadd_rn(__fmul_rn(f[2 * p + 0], 2.0f), -1.0f);
    float gy = __fadd_rn(__fmul_rn(f[2 * p + 1], 2.0f), -1.0f);
    float fx = __fmul_rn(__fadd_rn(__fmul_rn(__fadd_rn(gx, 1.0f), (float)GW), -1.0f), 0.5f);
    float fy = __fmul_rn(__fadd_rn(__fmul_rn(__fadd_rn(gy, 1.0f), (float)GW), -1.0f), 0.5f);
    int ix = (int)rintf(fx); ix = ix < 0 ? 0 : (ix > GW - 1 ? GW - 1 : ix);
    int iy = (int)rintf(fy); iy = iy < 0 ? 0 : (iy > GW - 1 ? GW - 1 : iy);
    int base = (iy * 3) * IMGW + ix * 3;
    if (i < NS) g_base_t[p] = base; else g_base_r[p] = base;
}

// ---------------- 2) refer patch channel mean: grid (49, 25), partial atomics ----------------
__global__ void k_mean(const float* __restrict__ rimg) {
    int c = blockIdx.x;
    int off = (c / 7) * IMGW + (c % 7);
    int t = threadIdx.x;
    int p = blockIdx.y * 256 + t;
    float s = rimg[g_base_r[p] + off];
#pragma unroll
    for (int o = 16; o; o >>= 1) s += __shfl_xor_sync(0xffffffffu, s, o);
    __shared__ float sw[8];
    if ((t & 31) == 0) sw[t >> 5] = s;
    __syncthreads();
    if (t == 0) {
        float x = 0.0f;
#pragma unroll
        for (int w = 0; w < 8; w++) x += sw[w];
        atomicAdd(&g_ymean[c], x * (1.0f / (float)NS));
    }
}

// ---------------- 3) features -> bf16 hi/lo split rows: 8 threads per patch ----------------
// X row: [hi(49) | hi(49) | lo(49) | 0] ; Y row: [hi(49) | lo(49) | hi(49) | 0]
// Block = 256 threads = 32 patches; grid (200, 2).
__global__ void __launch_bounds__(256) k_feat(const float* __restrict__ timg,
                                              const float* __restrict__ rimg) {
    __shared__ __nv_bfloat16 srow[32 * KST];    // 10752 B
    int t = threadIdx.x;
    int pl = t >> 3;                            // patch-in-block 0..31
    int s  = t & 7;                             // sub-thread 0..7 (row of patch)
    int p  = blockIdx.x * 32 + pl;
    bool is_t = (blockIdx.y == 0);
    const float* img = is_t ? timg : rimg;
    int base = is_t ? g_base_t[p] : g_base_r[p];

    float v[7];
    float sq = 0.0f;
    if (s < 7) {
        const float* rowp = img + base + s * IMGW;
#pragma unroll
        for (int i = 0; i < 7; i++) {
            v[i] = rowp[i] - g_ymean[s * 7 + i];
            sq += v[i] * v[i];
        }
    }
    // 8-lane reduction (width 8 subgroups within warp)
#pragma unroll
    for (int o = 4; o; o >>= 1) sq += __shfl_xor_sync(0xffffffffu, sq, o, 8);
    float inv = 1.0f / (sqrtf(sq) + EPSF);

    __nv_bfloat16* row = &srow[pl * KST];
    if (s < 7) {
#pragma unroll
        for (int i = 0; i < 7; i++) {
            int c = s * 7 + i;
            float val = v[i] * inv;
            __nv_bfloat16 hi = __float2bfloat16(val);
            __nv_bfloat16 lo = __float2bfloat16(val - __bfloat162float(hi));
            if (is_t) { row[c] = hi; row[49 + c] = hi; row[98 + c] = lo; }
            else      { row[c] = hi; row[49 + c] = lo; row[98 + c] = hi; }
        }
    } else {
        for (int k = 147; k < KST; k++) row[k] = __float2bfloat16(0.0f);
    }
    __syncthreads();

    // coalesced block copy: 32 rows x 21 uint4 contiguous
    uint4* dst = (uint4*)((is_t ? g_xr : g_yr) + (size_t)(blockIdx.x * 32) * KST);
    const uint4* src = (const uint4*)srow;
    for (int i = t; i < 32 * 21; i += 256) dst[i] = src[i];
}

// ---------------- 4) balanced persistent tensor GEMM (unchanged from R13) ----------------
#define SM_Y0   (128 * KST * 2)
#define SM_Y1   (192 * KST * 2)
#define SM_DS   (256 * KST * 2)
#define GEMM_SMEM (SM_DS + 128 * DPAD * 2)

__global__ void __launch_bounds__(256, 2) k_gemm() {
    extern __shared__ char smem[];
    uint32_t xs_u = smem_to_u32(smem);
    uint32_t y_u0 = xs_u + SM_Y0, y_u1 = xs_u + SM_Y1;
    __half* Ds = (__half*)(smem + SM_DS);
    int t = threadIdx.x, wid = t >> 5, lid = t & 31;
    int cta = blockIdx.x;
    int ts = (cta * NTILES) / NCTA;
    int te = ((cta + 1) * NTILES) / NCTA;
    int n = te - ts;                      // 16 or 17
    int cur_band = ts / 100;

    {
        const char* xsrc = (const char*)&g_xr[(size_t)(cur_band * 128) * KST];
        for (int i = t; i < 2688; i += 256) cp16(xs_u + i * 16, xsrc + (size_t)i * 16);
        const char* y0 = (const char*)&g_yr[(size_t)((ts % 100) * 64) * KST];
        for (int i = t; i < 1344; i += 256) cp16(y_u0 + i * 16, y0 + (size_t)i * 16);
        CP_COMMIT();
        if (n > 1) {
            const char* y1 = (const char*)&g_yr[(size_t)(((ts + 1) % 100) * 64) * KST];
            for (int i = t; i < 1344; i += 256) cp16(y_u1 + i * 16, y1 + (size_t)i * 16);
        }
        CP_COMMIT();
    }
    CP_WAIT(1);
    __syncthreads();

    int MR = (wid & 3) * 32, NC = (wid >> 2) * 32;
    int arow = (lid & 7) + ((lid >> 3) & 1) * 8;
    int akof = (lid >> 4) * 8;
    int brow = (lid & 7) + ((lid >> 4) & 1) * 8;
    int bkof = ((lid >> 3) & 1) * 8;
    int g = lid >> 2, tq = lid & 3;

    for (int it = 0; it < n; it++) {
        int tile = ts + it;
        int band = tile / 100, col = tile % 100;
        uint32_t yb = (it & 1) ? y_u1 : y_u0;

        if (band != cur_band) {           // <=1 time per CTA
            CP_WAIT(0);
            __syncthreads();
            const char* xsrc = (const char*)&g_xr[(size_t)(band * 128) * KST];
            for (int i = t; i < 2688; i += 256) cp16(xs_u + i * 16, xsrc + (size_t)i * 16);
            CP_COMMIT();
            CP_WAIT(0);
            __syncthreads();
            cur_band = band;
        }

        float acc[2][4][4];
#pragma unroll
        for (int i = 0; i < 2; i++)
#pragma unroll
            for (int j = 0; j < 4; j++)
#pragma unroll
                for (int e = 0; e < 4; e++) acc[i][j][e] = 0.0f;

#pragma unroll
        for (int k = 0; k < 10; k++) {
            int kb = k * 16;
            uint32_t a[2][4];
#pragma unroll
            for (int mt = 0; mt < 2; mt++)
                ldsm_x4(a[mt][0], a[mt][1], a[mt][2], a[mt][3],
                        xs_u + ((MR + mt * 16 + arow) * KST + kb + akof) * 2);
            uint32_t b[4][2];
#pragma unroll
            for (int nt2 = 0; nt2 < 2; nt2++)
                ldsm_x4(b[2 * nt2][0], b[2 * nt2][1], b[2 * nt2 + 1][0], b[2 * nt2 + 1][1],
                        yb + ((NC + nt2 * 16 + brow) * KST + kb + bkof) * 2);
#pragma unroll
            for (int mt = 0; mt < 2; mt++)
#pragma unroll
                for (int nt = 0; nt < 4; nt++)
                    mma16816(acc[mt][nt], a[mt], b[nt]);
        }

#pragma unroll
        for (int mt = 0; mt < 2; mt++) {
            int rl0 = MR + mt * 16 + g;
            int rl1 = rl0 + 8;
            float v0 = 1e30f, v1 = 1e30f;
            int i0 = 0, i1 = 0;
#pragma unroll
            for (int nt = 0; nt < 4; nt++) {
                int cl = NC + nt * 8 + tq * 2;
                int gcol = col * 64 + cl;
                float d00 = fmaxf(fmaf(acc[mt][nt][0], -0.5f, 0.5f), 0.0f);
                float d01 = fmaxf(fmaf(acc[mt][nt][1], -0.5f, 0.5f), 0.0f);
                float d10 = fmaxf(fmaf(acc[mt][nt][2], -0.5f, 0.5f), 0.0f);
                float d11 = fmaxf(fmaf(acc[mt][nt][3], -0.5f, 0.5f), 0.0f);
                uint32_t p0, p1;
                asm("cvt.rn.f16x2.f32 %0, %1, %2;" : "=r"(p0) : "f"(d01), "f"(d00));
                asm("cvt.rn.f16x2.f32 %0, %1, %2;" : "=r"(p1) : "f"(d11), "f"(d10));
                *(uint32_t*)&Ds[rl0 * DPAD + cl] = p0;
                *(uint32_t*)&Ds[rl1 * DPAD + cl] = p1;
                if (d00 < v0) { v0 = d00; i0 = gcol; }
                if (d01 < v0) { v0 = d01; i0 = gcol + 1; }
                if (d10 < v1) { v1 = d10; i1 = gcol; }
                if (d11 < v1) { v1 = d11; i1 = gcol + 1; }
            }
#pragma unroll
            for (int o = 1; o < 4; o <<= 1) {
                float vo0 = __shfl_xor_sync(0xffffffffu, v0, o);
                int   io0 = __shfl_xor_sync(0xffffffffu, i0, o);
                if (vo0 < v0 || (vo0 == v0 && io0 < i0)) { v0 = vo0; i0 = io0; }
                float vo1 = __shfl_xor_sync(0xffffffffu, v1, o);
                int   io1 = __shfl_xor_sync(0xffffffffu, i1, o);
                if (vo1 < v1 || (vo1 == v1 && io1 < i1)) { v1 = vo1; i1 = io1; }
            }
            if (tq == 0) {
                atomicMin(&g_amin[cur_band * 128 + rl0],
                          ((unsigned long long)__float_as_uint(v0) << 32) | (unsigned)i0);
                atomicMin(&g_amin[cur_band * 128 + rl1],
                          ((unsigned long long)__float_as_uint(v1) << 32) | (unsigned)i1);
            }
        }
        __syncthreads();

        if (it + 2 < n) {
            int coln = (tile + 2) % 100;
            const char* ysrc = (const char*)&g_yr[(size_t)(coln * 64) * KST];
            for (int i = t; i < 1344; i += 256) cp16(yb + i * 16, ysrc + (size_t)i * 16);
        }
        CP_COMMIT();

        for (int i = t; i < 1024; i += 256) {
            int row = i >> 3, c8 = i & 7;
            *(uint4*)&g_dh[(size_t)(cur_band * 128 + row) * NS + col * 64 + c8 * 8] =
                *(const uint4*)&Ds[row * DPAD + c8 * 8];
        }

        CP_WAIT(1);
        __syncthreads();
    }
}

// ---------------- 5) occurrence counts ----------------
__global__ void k_cnt() {
    int p = blockIdx.x * 256 + threadIdx.x;
    if (p < NS) {
        unsigned q = (unsigned)(g_amin[p] & 0xffffffffu);
        atomicAdd(&g_cnt[q], 1);
    }
}

// ---------------- 6) per-row min + sum-exp -> row loss (balanced ranges, 1 wave) ----------------
__global__ void __launch_bounds__(256) k_row() {
    extern __shared__ float dyn[];
    float* occ = dyn;               // [NS]
    float* sd  = dyn + NS;          // [NS]
    float* sr  = dyn + 2 * NS;      // [8]
    int t = threadIdx.x;
    int rs = (blockIdx.x * NS) / NROWCTA;
    int re = ((blockIdx.x + 1) * NS) / NROWCTA;

    for (int j = t; j < NS; j += 256) occ[j] = LAMB * (float)g_cnt[j];
    __syncthreads();

#pragma unroll 1
    for (int p = rs; p < re; p++) {
        const uint4* drow = (const uint4*)&g_dh[(size_t)p * NS];

        float m = 3.4e38f;
        for (int j8 = t; j8 < NS / 8; j8 += 256) {
            uint4 u = drow[j8];
            const __half2* h2 = (const __half2*)&u;
            int j = j8 * 8;
            float4 o0 = *(const float4*)&occ[j];
            float4 o1 = *(const float4*)&occ[j + 4];
            float2 a0 = __half22float2(h2[0]);
            float2 a1 = __half22float2(h2[1]);
            float2 a2 = __half22float2(h2[2]);
            float2 a3 = __half22float2(h2[3]);
            float4 f0 = make_float4(a0.x + o0.x, a0.y + o0.y, a1.x + o0.z, a1.y + o0.w);
            float4 f1 = make_float4(a2.x + o1.x, a2.y + o1.y, a3.x + o1.z, a3.y + o1.w);
            *(float4*)&sd[j]     = f0;
            *(float4*)&sd[j + 4] = f1;
            float m0 = fminf(fminf(f0.x, f0.y), fminf(f0.z, f0.w));
            float m1 = fminf(fminf(f1.x, f1.y), fminf(f1.z, f1.w));
            m = fminf(m, fminf(m0, m1));
        }
#pragma unroll
        for (int o = 16; o; o >>= 1) m = fminf(m, __shfl_xor_sync(0xffffffffu, m, o));
        if ((t & 31) == 0) sr[t >> 5] = m;
        __syncthreads();
        if (t == 0) {
            float x = sr[0];
#pragma unroll
            for (int w = 1; w < 8; w++) x = fminf(x, sr[w]);
            sr[0] = x;
        }
        __syncthreads();
        m = sr[0];
        __syncthreads();

        float meps = __fadd_rn(m, EPSF);
        float inv = 1.0f / meps;
        float nb = -L2E2 * inv;

        float s = 0.0f;
        for (int j = t; j < NS; j += 256)
            s += exp2f(fmaf(sd[j], nb, L2E2));
#pragma unroll
        for (int o = 16; o; o >>= 1) s += __shfl_xor_sync(0xffffffffu, s, o);
        if ((t & 31) == 0) sr[t >> 5] = s;
        __syncthreads();
        if (t == 0) {
            float st = 0.0f;
#pragma unroll
            for (int w = 0; w < 8; w++) st += sr[w];
            float emax = __fmul_rn(__fadd_rn(1.0f, -__fmul_rn(m, inv)), 2.0f);
            g_rowloss[p] = logf(st) - emax;
        }
        __syncthreads();
    }
}

// ---------------- 7) final mean ----------------
__global__ void k_final(float* __restrict__ out) {
    int t = threadIdx.x;
    float s = 0.0f;
    for (int p = t; p < NS; p += 256) s += g_rowloss[p];
    __shared__ float sm[256];
    sm[t] = s; __syncthreads();
    for (int st = 128; st; st >>= 1) { if (t < st) sm[t] += sm[t + st]; __syncthreads(); }
    if (t == 0) out[0] = sm[0] * (1.0f / (float)NS);
}

// ---------------- host launch ----------------
extern "C" void kernel_launch(void* const* d_in, const int* in_sizes, int n_in,
                              void* d_out, int out_size) {
    (void)in_sizes; (void)n_in; (void)out_size;
    const float* timg   = (const float*)d_in[0];
    const float* rimg   = (const float*)d_in[1];
    const float* tfield = (const float*)d_in[2];
    const float* rfield = (const float*)d_in[3];
    float* out = (float*)d_out;

    const int ROW_SMEM = (2 * NS + 8) * (int)sizeof(float);          // 51232 B
    cudaFuncSetAttribute(k_gemm, cudaFuncAttributeMaxDynamicSharedMemorySize, GEMM_SMEM);
    cudaFuncSetAttribute(k_row,  cudaFuncAttributeMaxDynamicSharedMemorySize, ROW_SMEM);

    k_idx  <<<50, 256>>>(tfield, rfield);
    k_mean <<<dim3(CCH, 25), 256>>>(rimg);
    k_feat <<<dim3(200, 2), 256>>>(timg, rimg);
    k_gemm <<<NCTA, 256, GEMM_SMEM>>>();
    k_cnt  <<<25, 256>>>();
    k_row  <<<NROWCTA, 256, ROW_SMEM>>>();
    k_final<<<1, 256>>>(out);
}

// round 17
// speedup vs baseline: 1.4510x; 1.0005x over previous
#include <cuda_runtime.h>
#include <cuda_fp16.h>
#include <cuda_bf16.h>
#include <cstdint>
#include <math.h>

// ---------------- problem constants ----------------
#define NS    6400          // SAMPLE*SAMPLE patches per image
#define CCH   49            // PATCH*PATCH channels
#define IMGW  512
#define GW    169           // (512-7)/3 + 1 patch-grid size
#define EPSF  2.2204460492503131e-16f
#define LAMB  0.05f
#define KST   168           // row stride in bf16 (160 active K + 8 pad)
#define DPAD2 136           // d staging row stride in halves (128 + 8 pad)
#define NTIL2 2500          // 50 row bands x 50 col tiles (128x128)
#define NCTA2 148           // 1 CTA per SM, one wave
#define NROWCTA 592         // 4 CTAs x 148 SMs, one wave (k_row)
#define L2E2  2.8853900817779268f   // 2*log2(e)

// ---------------- device scratch ----------------
__device__ int   g_base_t[NS];
__device__ int   g_base_r[NS];
__device__ float g_ymean[CCH];
__device__ __nv_bfloat16 g_xr[(size_t)NS * KST];  // target rows [hi49|hi49|lo49|0...]
__device__ __nv_bfloat16 g_yr[(size_t)NS * KST];  // refer  rows [hi49|lo49|hi49|0...]
__device__ __half g_dh[(size_t)NS * NS];          // 81.92 MB distance matrix (fp16)
__device__ unsigned long long g_amin[NS];
__device__ int   g_cnt[NS];
__device__ float g_rowloss[NS];

// ---------------- helpers ----------------
__device__ __forceinline__ uint32_t smem_to_u32(const void* p) {
    uint32_t a;
    asm("{ .reg .u64 t; cvta.to.shared.u64 t, %1; cvt.u32.u64 %0, t; }" : "=r"(a) : "l"(p));
    return a;
}
__device__ __forceinline__ void ldsm_x4(uint32_t& r0, uint32_t& r1, uint32_t& r2, uint32_t& r3,
                                        uint32_t addr) {
    asm volatile("ldmatrix.sync.aligned.m8n8.x4.shared.b16 {%0,%1,%2,%3}, [%4];"
                 : "=r"(r0), "=r"(r1), "=r"(r2), "=r"(r3) : "r"(addr));
}
__device__ __forceinline__ void mma16816(float* c, const uint32_t* a, const uint32_t* b) {
    asm volatile("mma.sync.aligned.m16n8k16.row.col.f32.bf16.bf16.f32 "
                 "{%0,%1,%2,%3}, {%4,%5,%6,%7}, {%8,%9}, {%0,%1,%2,%3};"
                 : "+f"(c[0]), "+f"(c[1]), "+f"(c[2]), "+f"(c[3])
                 : "r"(a[0]), "r"(a[1]), "r"(a[2]), "r"(a[3]), "r"(b[0]), "r"(b[1]));
}
__device__ __forceinline__ void cp16(uint32_t dst, const void* src) {
    asm volatile("cp.async.cg.shared.global [%0], [%1], 16;" :: "r"(dst), "l"(src));
}
#define CP_COMMIT() asm volatile("cp.async.commit_group;" ::: "memory")
#define CP_WAIT(n)  asm volatile("cp.async.wait_group %0;" :: "n"(n) : "memory")

// ---------------- 1) grid-sample nearest indices (+ init amin/cnt/ymean) ----------------
__global__ void k_idx(const float* __restrict__ tfield, const float* __restrict__ rfield) {
    int i = blockIdx.x * blockDim.x + threadIdx.x;
    if (i < NS) { g_amin[i] = ~0ull; g_cnt[i] = 0; }
    if (i < CCH) g_ymean[i] = 0.0f;
    if (i >= 2 * NS) return;
    const float* f = (i < NS) ? tfield : rfield;
    int p = (i < NS) ? i : (i - NS);
    float gx = __fadd_rn(__fmul_rn(f[2 * p + 0], 2.0f), -1.0f);
    float gy = __fadd_rn(__fmul_rn(f[2 * p + 1], 2.0f), -1.0f);
    float fx = __fmul_rn(__fadd_rn(__fmul_rn(__fadd_rn(gx, 1.0f), (float)GW), -1.0f), 0.5f);
    float fy = __fmul_rn(__fadd_rn(__fmul_rn(__fadd_rn(gy, 1.0f), (float)GW), -1.0f), 0.5f);
    int ix = (int)rintf(fx); ix = ix < 0 ? 0 : (ix > GW - 1 ? GW - 1 : ix);
    int iy = (int)rintf(fy); iy = iy < 0 ? 0 : (iy > GW - 1 ? GW - 1 : iy);
    int base = (iy * 3) * IMGW + ix * 3;
    if (i < NS) g_base_t[p] = base; else g_base_r[p] = base;
}

// ---------------- 2) refer patch channel mean: grid (49, 25), partial atomics ----------------
__global__ void k_mean(const float* __restrict__ rimg) {
    int c = blockIdx.x;
    int off = (c / 7) * IMGW + (c % 7);
    int t = threadIdx.x;
    int p = blockIdx.y * 256 + t;
    float s = rimg[g_base_r[p] + off];
#pragma unroll
    for (int o = 16; o; o >>= 1) s += __shfl_xor_sync(0xffffffffu, s, o);
    __shared__ float sw[8];
    if ((t & 31) == 0) sw[t >> 5] = s;
    __syncthreads();
    if (t == 0) {
        float x = 0.0f;
#pragma unroll
        for (int w = 0; w < 8; w++) x += sw[w];
        atomicAdd(&g_ymean[c], x * (1.0f / (float)NS));
    }
}

// ---------------- 3) features -> bf16 hi/lo split rows: 8 threads per patch ----------------
__global__ void __launch_bounds__(256) k_feat(const float* __restrict__ timg,
                                              const float* __restrict__ rimg) {
    __shared__ __nv_bfloat16 srow[32 * KST];    // 10752 B
    int t = threadIdx.x;
    int pl = t >> 3;                            // patch-in-block 0..31
    int s  = t & 7;                             // sub-thread 0..7 (row of patch)
    int p  = blockIdx.x * 32 + pl;
    bool is_t = (blockIdx.y == 0);
    const float* img = is_t ? timg : rimg;
    int base = is_t ? g_base_t[p] : g_base_r[p];

    float v[7];
    float sq = 0.0f;
    if (s < 7) {
        const float* rowp = img + base + s * IMGW;
#pragma unroll
        for (int i = 0; i < 7; i++) {
            v[i] = rowp[i] - g_ymean[s * 7 + i];
            sq += v[i] * v[i];
        }
    }
#pragma unroll
    for (int o = 4; o; o >>= 1) sq += __shfl_xor_sync(0xffffffffu, sq, o, 8);
    float inv = 1.0f / (sqrtf(sq) + EPSF);

    __nv_bfloat16* row = &srow[pl * KST];
    if (s < 7) {
#pragma unroll
        for (int i = 0; i < 7; i++) {
            int c = s * 7 + i;
            float val = v[i] * inv;
            __nv_bfloat16 hi = __float2bfloat16(val);
            __nv_bfloat16 lo = __float2bfloat16(val - __bfloat162float(hi));
            if (is_t) { row[c] = hi; row[49 + c] = hi; row[98 + c] = lo; }
            else      { row[c] = hi; row[49 + c] = lo; row[98 + c] = hi; }
        }
    } else {
        for (int k = 147; k < KST; k++) row[k] = __float2bfloat16(0.0f);
    }
    __syncthreads();

    uint4* dst = (uint4*)((is_t ? g_xr : g_yr) + (size_t)(blockIdx.x * 32) * KST);
    const uint4* src = (const uint4*)srow;
    for (int i = t; i < 32 * 21; i += 256) dst[i] = src[i];
}

// ---------------- 4) balanced persistent tensor GEMM: 128x128 tiles, 1 CTA/SM ----------------
// 148 CTAs; CTA c owns contiguous tiles [c*2500/148, (c+1)*2500/148) band-major
// (band = t/50 -> 128 rows; col = t%50 -> 128 cols). 8 warps: 4 m-bands x 2 n-bands (32x64).
// smem: X 43008 | Y0 43008 | Y1 43008 | Ds 34816 = 163840 B
#define SM_YA   (128 * KST * 2)
#define SM_YB   (256 * KST * 2)
#define SM_DS2  (384 * KST * 2)
#define GEMM_SMEM (SM_DS2 + 128 * DPAD2 * 2)

__global__ void __launch_bounds__(256, 1) k_gemm() {
    extern __shared__ char smem[];
    uint32_t xs_u = smem_to_u32(smem);
    uint32_t y_u0 = xs_u + SM_YA, y_u1 = xs_u + SM_YB;
    __half* Ds = (__half*)(smem + SM_DS2);
    int t = threadIdx.x, wid = t >> 5, lid = t & 31;
    int cta = blockIdx.x;
    int ts = (cta * NTIL2) / NCTA2;
    int te = ((cta + 1) * NTIL2) / NCTA2;
    int n = te - ts;                      // 16 or 17
    int cur_band = ts / 50;

    // prologue: group1 = X(cur_band) + Y(tile0); group2 = Y(tile1) (or empty)
    {
        const char* xsrc = (const char*)&g_xr[(size_t)(cur_band * 128) * KST];
        for (int i = t; i < 2688; i += 256) cp16(xs_u + i * 16, xsrc + (size_t)i * 16);
        const char* y0 = (const char*)&g_yr[(size_t)((ts % 50) * 128) * KST];
        for (int i = t; i < 2688; i += 256) cp16(y_u0 + i * 16, y0 + (size_t)i * 16);
        CP_COMMIT();
        if (n > 1) {
            const char* y1 = (const char*)&g_yr[(size_t)(((ts + 1) % 50) * 128) * KST];
            for (int i = t; i < 2688; i += 256) cp16(y_u1 + i * 16, y1 + (size_t)i * 16);
        }
        CP_COMMIT();
    }
    CP_WAIT(1);
    __syncthreads();

    int MR = (wid & 3) * 32, NC = (wid >> 2) * 64;
    int arow = (lid & 7) + ((lid >> 3) & 1) * 8;
    int akof = (lid >> 4) * 8;
    int brow = (lid & 7) + ((lid >> 4) & 1) * 8;
    int bkof = ((lid >> 3) & 1) * 8;
    int g = lid >> 2, tq = lid & 3;

    for (int it = 0; it < n; it++) {
        int tile = ts + it;
        int band = tile / 50, col = tile % 50;
        uint32_t yb = (it & 1) ? y_u1 : y_u0;

        if (band != cur_band) {           // <=1 time per CTA
            CP_WAIT(0);
            __syncthreads();
            const char* xsrc = (const char*)&g_xr[(size_t)(band * 128) * KST];
            for (int i = t; i < 2688; i += 256) cp16(xs_u + i * 16, xsrc + (size_t)i * 16);
            CP_COMMIT();
            CP_WAIT(0);
            __syncthreads();
            cur_band = band;
        }

        float acc[2][8][4];
#pragma unroll
        for (int i = 0; i < 2; i++)
#pragma unroll
            for (int j = 0; j < 8; j++)
#pragma unroll
                for (int e = 0; e < 4; e++) acc[i][j][e] = 0.0f;

#pragma unroll
        for (int k = 0; k < 10; k++) {
            int kb = k * 16;
            uint32_t a[2][4];
#pragma unroll
            for (int mt = 0; mt < 2; mt++)
                ldsm_x4(a[mt][0], a[mt][1], a[mt][2], a[mt][3],
                        xs_u + ((MR + mt * 16 + arow) * KST + kb + akof) * 2);
            uint32_t b[8][2];
#pragma unroll
            for (int nt2 = 0; nt2 < 4; nt2++)
                ldsm_x4(b[2 * nt2][0], b[2 * nt2][1], b[2 * nt2 + 1][0], b[2 * nt2 + 1][1],
                        yb + ((NC + nt2 * 16 + brow) * KST + kb + bkof) * 2);
#pragma unroll
            for (int mt = 0; mt < 2; mt++)
#pragma unroll
                for (int nt = 0; nt < 8; nt++)
                    mma16816(acc[mt][nt], a[mt], b[nt]);
        }

        // epilogue: d = max(0.5 - 0.5*sim, 0) -> Ds (smem) + global packed-key argmin
#pragma unroll
        for (int mt = 0; mt < 2; mt++) {
            int rl0 = MR + mt * 16 + g;
            int rl1 = rl0 + 8;
            float v0 = 1e30f, v1 = 1e30f;
            int i0 = 0, i1 = 0;
#pragma unroll
            for (int nt = 0; nt < 8; nt++) {
                int cl = NC + nt * 8 + tq * 2;
                int gcol = col * 128 + cl;
                float d00 = fmaxf(fmaf(acc[mt][nt][0], -0.5f, 0.5f), 0.0f);
                float d01 = fmaxf(fmaf(acc[mt][nt][1], -0.5f, 0.5f), 0.0f);
                float d10 = fmaxf(fmaf(acc[mt][nt][2], -0.5f, 0.5f), 0.0f);
                float d11 = fmaxf(fmaf(acc[mt][nt][3], -0.5f, 0.5f), 0.0f);
                uint32_t p0, p1;
                asm("cvt.rn.f16x2.f32 %0, %1, %2;" : "=r"(p0) : "f"(d01), "f"(d00));
                asm("cvt.rn.f16x2.f32 %0, %1, %2;" : "=r"(p1) : "f"(d11), "f"(d10));
                *(uint32_t*)&Ds[rl0 * DPAD2 + cl] = p0;
                *(uint32_t*)&Ds[rl1 * DPAD2 + cl] = p1;
                if (d00 < v0) { v0 = d00; i0 = gcol; }
                if (d01 < v0) { v0 = d01; i0 = gcol + 1; }
                if (d10 < v1) { v1 = d10; i1 = gcol; }
                if (d11 < v1) { v1 = d11; i1 = gcol + 1; }
            }
#pragma unroll
            for (int o = 1; o < 4; o <<= 1) {
                float vo0 = __shfl_xor_sync(0xffffffffu, v0, o);
                int   io0 = __shfl_xor_sync(0xffffffffu, i0, o);
                if (vo0 < v0 || (vo0 == v0 && io0 < i0)) { v0 = vo0; i0 = io0; }
                float vo1 = __shfl_xor_sync(0xffffffffu, v1, o);
                int   io1 = __shfl_xor_sync(0xffffffffu, i1, o);
                if (vo1 < v1 || (vo1 == v1 && io1 < i1)) { v1 = vo1; i1 = io1; }
            }
            if (tq == 0) {
                atomicMin(&g_amin[cur_band * 128 + rl0],
                          ((unsigned long long)__float_as_uint(v0) << 32) | (unsigned)i0);
                atomicMin(&g_amin[cur_band * 128 + rl1],
                          ((unsigned long long)__float_as_uint(v1) << 32) | (unsigned)i1);
            }
        }
        __syncthreads();    // Y[cur] fully read; Ds fully written

        // prefetch tile it+2 into the buffer just consumed
        if (it + 2 < n) {
            int coln = (tile + 2) % 50;
            const char* ysrc = (const char*)&g_yr[(size_t)(coln * 128) * KST];
            for (int i = t; i < 2688; i += 256) cp16(yb + i * 16, ysrc + (size_t)i * 16);
        }
        CP_COMMIT();

        // coalesced store of this tile: 128 rows x 16 uint4 (256 B/row)
        for (int i = t; i < 2048; i += 256) {
            int row = i >> 4, c16 = i & 15;
            *(uint4*)&g_dh[(size_t)(cur_band * 128 + row) * NS + col * 128 + c16 * 8] =
                *(const uint4*)&Ds[row * DPAD2 + c16 * 8];
        }

        CP_WAIT(1);
        __syncthreads();
    }
}

// ---------------- 5) occurrence counts ----------------
__global__ void k_cnt() {
    int p = blockIdx.x * 256 + threadIdx.x;
    if (p < NS) {
        unsigned q = (unsigned)(g_amin[p] & 0xffffffffu);
        atomicAdd(&g_cnt[q], 1);
    }
}

// ---------------- 6) per-row min + sum-exp -> row loss (balanced ranges, 1 wave) ----------------
__global__ void __launch_bounds__(256) k_row() {
    extern __shared__ float dyn[];
    float* occ = dyn;               // [NS]
    float* sd  = dyn + NS;          // [NS]
    float* sr  = dyn + 2 * NS;      // [8]
    int t = threadIdx.x;
    int rs = (blockIdx.x * NS) / NROWCTA;
    int re = ((blockIdx.x + 1) * NS) / NROWCTA;

    for (int j = t; j < NS; j += 256) occ[j] = LAMB * (float)g_cnt[j];
    __syncthreads();

#pragma unroll 1
    for (int p = rs; p < re; p++) {
        const uint4* drow = (const uint4*)&g_dh[(size_t)p * NS];

        float m = 3.4e38f;
        for (int j8 = t; j8 < NS / 8; j8 += 256) {
            uint4 u = drow[j8];
            const __half2* h2 = (const __half2*)&u;
            int j = j8 * 8;
            float4 o0 = *(const float4*)&occ[j];
            float4 o1 = *(const float4*)&occ[j + 4];
            float2 a0 = __half22float2(h2[0]);
            float2 a1 = __half22float2(h2[1]);
            float2 a2 = __half22float2(h2[2]);
            float2 a3 = __half22float2(h2[3]);
            float4 f0 = make_float4(a0.x + o0.x, a0.y + o0.y, a1.x + o0.z, a1.y + o0.w);
            float4 f1 = make_float4(a2.x + o1.x, a2.y + o1.y, a3.x + o1.z, a3.y + o1.w);
            *(float4*)&sd[j]     = f0;
            *(float4*)&sd[j + 4] = f1;
            float m0 = fminf(fminf(f0.x, f0.y), fminf(f0.z, f0.w));
            float m1 = fminf(fminf(f1.x, f1.y), fminf(f1.z, f1.w));
            m = fminf(m, fminf(m0, m1));
        }
#pragma unroll
        for (int o = 16; o; o >>= 1) m = fminf(m, __shfl_xor_sync(0xffffffffu, m, o));
        if ((t & 31) == 0) sr[t >> 5] = m;
        __syncthreads();
        if (t == 0) {
            float x = sr[0];
#pragma unroll
            for (int w = 1; w < 8; w++) x = fminf(x, sr[w]);
            sr[0] = x;
        }
        __syncthreads();
        m = sr[0];
        __syncthreads();

        float meps = __fadd_rn(m, EPSF);
        float inv = 1.0f / meps;
        float nb = -L2E2 * inv;

        float s = 0.0f;
        for (int j = t; j < NS; j += 256)
            s += exp2f(fmaf(sd[j], nb, L2E2));
#pragma unroll
        for (int o = 16; o; o >>= 1) s += __shfl_xor_sync(0xffffffffu, s, o);
        if ((t & 31) == 0) sr[t >> 5] = s;
        __syncthreads();
        if (t == 0) {
            float st = 0.0f;
#pragma unroll
            for (int w = 0; w < 8; w++) st += sr[w];
            float emax = __fmul_rn(__fadd_rn(1.0f, -__fmul_rn(m, inv)), 2.0f);
            g_rowloss[p] = logf(st) - emax;
        }
        __syncthreads();
    }
}

// ---------------- 7) final mean ----------------
__global__ void k_final(float* __restrict__ out) {
    int t = threadIdx.x;
    float s = 0.0f;
    for (int p = t; p < NS; p += 256) s += g_rowloss[p];
    __shared__ float sm[256];
    sm[t] = s; __syncthreads();
    for (int st = 128; st; st >>= 1) { if (t < st) sm[t] += sm[t + st]; __syncthreads(); }
    if (t == 0) out[0] = sm[0] * (1.0f / (float)NS);
}

// ---------------- host launch ----------------
extern "C" void kernel_launch(void* const* d_in, const int* in_sizes, int n_in,
                              void* d_out, int out_size) {
    (void)in_sizes; (void)n_in; (void)out_size;
    const float* timg   = (const float*)d_in[0];
    const float* rimg   = (const float*)d_in[1];
    const float* tfield = (const float*)d_in[2];
    const float* rfield = (const float*)d_in[3];
    float* out = (float*)d_out;

    const int ROW_SMEM = (2 * NS + 8) * (int)sizeof(float);          // 51232 B
    cudaFuncSetAttribute(k_gemm, cudaFuncAttributeMaxDynamicSharedMemorySize, GEMM_SMEM);
    cudaFuncSetAttribute(k_row,  cudaFuncAttributeMaxDynamicSharedMemorySize, ROW_SMEM);

    k_idx  <<<50, 256>>>(tfield, rfield);
    k_mean <<<dim3(CCH, 25), 256>>>(rimg);
    k_feat <<<dim3(200, 2), 256>>>(timg, rimg);
    k_gemm <<<NCTA2, 256, GEMM_SMEM>>>();
    k_cnt  <<<25, 256>>>();
    k_row  <<<NROWCTA, 256, ROW_SMEM>>>();
    k_final<<<1, 256>>>(out);
}